// round 1
// baseline (speedup 1.0000x reference)
#include <cuda_runtime.h>
#include <cstddef>

#define B_   4
#define NSEQ 2048
#define CD   256
#define ICH  128
#define M2   4096   // 2*NSEQ
#define LIN_ELEMS  (B_*NSEQ*CD)       // 2,097,152
#define PERM_ELEMS (B_*M2*ICH)        // 2,097,152
#define F_ELEMS    ((size_t)B_*M2*M2) // 67,108,864 (256 MB)

// Scratch (device globals; no allocation allowed)
__device__ float d_theta[LIN_ELEMS];
__device__ float d_phi  [LIN_ELEMS];
__device__ float d_g    [LIN_ELEMS];
__device__ float d_g2   [LIN_ELEMS];
__device__ float d_T [PERM_ELEMS];
__device__ float d_P [PERM_ELEMS];
__device__ float d_D [PERM_ELEMS];
__device__ float d_A [PERM_ELEMS];
__device__ float d_f [F_ELEMS];
__device__ float d_na[PERM_ELEMS];
__device__ float d_nd[PERM_ELEMS];
__device__ float d_Gna[LIN_ELEMS];
__device__ float d_Gnd[LIN_ELEMS];

// ---------------------------------------------------------------------------
// Y[M,256] = X[M,256] @ W[256,256]^T + bias (+ res). M = B_*NSEQ = 8192.
// 64x64 tile, 256 threads, 4x4 per thread, KC=16.
// ---------------------------------------------------------------------------
__global__ __launch_bounds__(256) void lin_kernel(
    const float* __restrict__ X, const float* __restrict__ W,
    const float* __restrict__ bias, const float* __restrict__ res,
    float* __restrict__ Y)
{
    __shared__ float As[16][68];
    __shared__ float Bs[16][68];
    const int m0 = blockIdx.x * 64, n0 = blockIdx.y * 64;
    const int tid = threadIdx.x;
    const int tx = tid & 15, ty = tid >> 4;
    const int lm = tid >> 2;           // 0..63
    const int lk = (tid & 3) * 4;      // 0,4,8,12
    float acc[4][4] = {};

    for (int k0 = 0; k0 < CD; k0 += 16) {
        float4 av = *(const float4*)&X[(size_t)(m0 + lm) * CD + k0 + lk];
        float4 bv = *(const float4*)&W[(size_t)(n0 + lm) * CD + k0 + lk];
        As[lk + 0][lm] = av.x; As[lk + 1][lm] = av.y;
        As[lk + 2][lm] = av.z; As[lk + 3][lm] = av.w;
        Bs[lk + 0][lm] = bv.x; Bs[lk + 1][lm] = bv.y;
        Bs[lk + 2][lm] = bv.z; Bs[lk + 3][lm] = bv.w;
        __syncthreads();
#pragma unroll
        for (int k = 0; k < 16; k++) {
            float a[4], b[4];
#pragma unroll
            for (int i = 0; i < 4; i++) { a[i] = As[k][ty * 4 + i]; b[i] = Bs[k][tx * 4 + i]; }
#pragma unroll
            for (int i = 0; i < 4; i++)
#pragma unroll
                for (int j = 0; j < 4; j++) acc[i][j] += a[i] * b[j];
        }
        __syncthreads();
    }
#pragma unroll
    for (int i = 0; i < 4; i++) {
        const int m = m0 + ty * 4 + i;
#pragma unroll
        for (int j = 0; j < 4; j++) {
            const int n = n0 + tx * 4 + j;
            float v = acc[i][j] + bias[n];
            if (res) v += res[(size_t)m * CD + n];
            Y[(size_t)m * CD + n] = v;
        }
    }
}

// ---------------------------------------------------------------------------
// Per-batch transpose: in (R,C) -> out (C,R). grid = (C/32, R/32, B_), block (32,8)
// ---------------------------------------------------------------------------
__global__ void transpose_kernel(const float* __restrict__ in, float* __restrict__ out,
                                 int R, int C)
{
    __shared__ float tile[32][33];
    const int b = blockIdx.z;
    const float* inb = in + (size_t)b * R * C;
    float* outb = out + (size_t)b * R * C;
    const int c0 = blockIdx.x * 32, r0 = blockIdx.y * 32;
    const int tx = threadIdx.x, ty = threadIdx.y;
#pragma unroll
    for (int i = 0; i < 32; i += 8)
        tile[ty + i][tx] = inb[(size_t)(r0 + ty + i) * C + c0 + tx];
    __syncthreads();
#pragma unroll
    for (int i = 0; i < 32; i += 8)
        outb[(size_t)(c0 + ty + i) * R + r0 + tx] = tile[tx][ty + i];
}

// ---------------------------------------------------------------------------
// f[p,q] = (1/4096) * sum_k T[p,k]*P[q,k].  128x128 tile, 256 thr, 8x8, K=128.
// grid = (32, 32, B_)
// ---------------------------------------------------------------------------
__global__ __launch_bounds__(256) void gemmf_kernel()
{
    __shared__ float As[16][132];
    __shared__ float Bs[16][132];
    const int b = blockIdx.z;
    const float* Tb = d_T + (size_t)b * M2 * ICH;
    const float* Pb = d_P + (size_t)b * M2 * ICH;
    float* fb = d_f + (size_t)b * M2 * M2;
    const int p0 = blockIdx.x * 128, q0 = blockIdx.y * 128;
    const int tid = threadIdx.x;
    const int tx = tid & 15, ty = tid >> 4;
    const int lm = tid >> 1;            // 0..127
    const int lk = (tid & 1) * 8;       // 0 or 8
    float acc[8][8] = {};

    for (int k0 = 0; k0 < ICH; k0 += 16) {
        float4 a0 = *(const float4*)&Tb[(size_t)(p0 + lm) * ICH + k0 + lk];
        float4 a1 = *(const float4*)&Tb[(size_t)(p0 + lm) * ICH + k0 + lk + 4];
        float4 b0 = *(const float4*)&Pb[(size_t)(q0 + lm) * ICH + k0 + lk];
        float4 b1 = *(const float4*)&Pb[(size_t)(q0 + lm) * ICH + k0 + lk + 4];
        As[lk + 0][lm] = a0.x; As[lk + 1][lm] = a0.y; As[lk + 2][lm] = a0.z; As[lk + 3][lm] = a0.w;
        As[lk + 4][lm] = a1.x; As[lk + 5][lm] = a1.y; As[lk + 6][lm] = a1.z; As[lk + 7][lm] = a1.w;
        Bs[lk + 0][lm] = b0.x; Bs[lk + 1][lm] = b0.y; Bs[lk + 2][lm] = b0.z; Bs[lk + 3][lm] = b0.w;
        Bs[lk + 4][lm] = b1.x; Bs[lk + 5][lm] = b1.y; Bs[lk + 6][lm] = b1.z; Bs[lk + 7][lm] = b1.w;
        __syncthreads();
#pragma unroll
        for (int k = 0; k < 16; k++) {
            float a[8], b[8];
#pragma unroll
            for (int i = 0; i < 8; i++) { a[i] = As[k][ty * 8 + i]; b[i] = Bs[k][tx * 8 + i]; }
#pragma unroll
            for (int i = 0; i < 8; i++)
#pragma unroll
                for (int j = 0; j < 8; j++) acc[i][j] += a[i] * b[j];
        }
        __syncthreads();
    }
    const float s = 1.0f / 4096.0f;
#pragma unroll
    for (int i = 0; i < 8; i++) {
        float* row = &fb[(size_t)(p0 + ty * 8 + i) * M2 + q0 + tx * 8];
        float4 v0 = make_float4(acc[i][0] * s, acc[i][1] * s, acc[i][2] * s, acc[i][3] * s);
        float4 v1 = make_float4(acc[i][4] * s, acc[i][5] * s, acc[i][6] * s, acc[i][7] * s);
        *(float4*)(row) = v0;
        *(float4*)(row + 4) = v1;
    }
}

// ---------------------------------------------------------------------------
// mode 0 (NN): na[p,i] = sum_q f[p,q]*D[q,i]
// mode 1 (TN): nd[q,i] = sum_p f[p,q]*A[p,i]
// 64(m) x 128(n) tile, 256 thr, 4x8, K=4096, KC=16. grid = (64, 2, B_)
// ---------------------------------------------------------------------------
__global__ __launch_bounds__(256) void gemm2_kernel()
{
    __shared__ float Fs[16][68];
    __shared__ float Ds[16][132];
    const int b = blockIdx.z;
    const int mode = blockIdx.y;
    const float* fb = d_f + (size_t)b * M2 * M2;
    const float* Xb = (mode == 0 ? d_D : d_A) + (size_t)b * M2 * ICH;
    float* Yb = (mode == 0 ? d_na : d_nd) + (size_t)b * M2 * ICH;
    const int m0 = blockIdx.x * 64;
    const int tid = threadIdx.x;
    const int tx = tid & 15, ty = tid >> 4;
    float acc[4][8] = {};

    for (int k0 = 0; k0 < M2; k0 += 16) {
        if (mode == 0) {
            const int lm = tid >> 2, lk = (tid & 3) * 4;
            float4 v = *(const float4*)&fb[(size_t)(m0 + lm) * M2 + k0 + lk];
            Fs[lk + 0][lm] = v.x; Fs[lk + 1][lm] = v.y;
            Fs[lk + 2][lm] = v.z; Fs[lk + 3][lm] = v.w;
        } else {
            const int lk = tid >> 4, lm = (tid & 15) * 4;
            float4 v = *(const float4*)&fb[(size_t)(k0 + lk) * M2 + m0 + lm];
            Fs[lk][lm + 0] = v.x; Fs[lk][lm + 1] = v.y;
            Fs[lk][lm + 2] = v.z; Fs[lk][lm + 3] = v.w;
        }
        {
            const int lk = tid >> 4, ln = (tid & 15) * 8;
            float4 v0 = *(const float4*)&Xb[(size_t)(k0 + lk) * ICH + ln];
            float4 v1 = *(const float4*)&Xb[(size_t)(k0 + lk) * ICH + ln + 4];
            Ds[lk][ln + 0] = v0.x; Ds[lk][ln + 1] = v0.y; Ds[lk][ln + 2] = v0.z; Ds[lk][ln + 3] = v0.w;
            Ds[lk][ln + 4] = v1.x; Ds[lk][ln + 5] = v1.y; Ds[lk][ln + 6] = v1.z; Ds[lk][ln + 7] = v1.w;
        }
        __syncthreads();
#pragma unroll
        for (int k = 0; k < 16; k++) {
            float a[4], b[8];
#pragma unroll
            for (int i = 0; i < 4; i++) a[i] = Fs[k][ty * 4 + i];
#pragma unroll
            for (int j = 0; j < 8; j++) b[j] = Ds[k][tx * 8 + j];
#pragma unroll
            for (int i = 0; i < 4; i++)
#pragma unroll
                for (int j = 0; j < 8; j++) acc[i][j] += a[i] * b[j];
        }
        __syncthreads();
    }
#pragma unroll
    for (int i = 0; i < 4; i++) {
        float* row = &Yb[(size_t)(m0 + ty * 4 + i) * ICH + tx * 8];
        *(float4*)(row)     = make_float4(acc[i][0], acc[i][1], acc[i][2], acc[i][3]);
        *(float4*)(row + 4) = make_float4(acc[i][4], acc[i][5], acc[i][6], acc[i][7]);
    }
}

// ---------------------------------------------------------------------------
extern "C" void kernel_launch(void* const* d_in, const int* in_sizes, int n_in,
                              void* d_out, int out_size)
{
    const float* detect = (const float*)d_in[0];
    const float* aim    = (const float*)d_in[1];
    const float* g_w  = (const float*)d_in[2];  const float* g_b  = (const float*)d_in[3];
    const float* g2_w = (const float*)d_in[4];  const float* g2_b = (const float*)d_in[5];
    const float* th_w = (const float*)d_in[6];  const float* th_b = (const float*)d_in[7];
    const float* ph_w = (const float*)d_in[8];  const float* ph_b = (const float*)d_in[9];
    const float* W_w  = (const float*)d_in[10]; const float* W_b  = (const float*)d_in[11];
    const float* Q_w  = (const float*)d_in[12]; const float* Q_b  = (const float*)d_in[13];

    float* out_det = (float*)d_out;                      // non_det first
    float* out_aim = out_det + (size_t)B_ * NSEQ * CD;   // then non_aim

    float *p_theta, *p_phi, *p_g, *p_g2, *p_T, *p_P, *p_D, *p_A, *p_na, *p_nd, *p_Gna, *p_Gnd;
    cudaGetSymbolAddress((void**)&p_theta, d_theta);
    cudaGetSymbolAddress((void**)&p_phi,   d_phi);
    cudaGetSymbolAddress((void**)&p_g,     d_g);
    cudaGetSymbolAddress((void**)&p_g2,    d_g2);
    cudaGetSymbolAddress((void**)&p_T,     d_T);
    cudaGetSymbolAddress((void**)&p_P,     d_P);
    cudaGetSymbolAddress((void**)&p_D,     d_D);
    cudaGetSymbolAddress((void**)&p_A,     d_A);
    cudaGetSymbolAddress((void**)&p_na,    d_na);
    cudaGetSymbolAddress((void**)&p_nd,    d_nd);
    cudaGetSymbolAddress((void**)&p_Gna,   d_Gna);
    cudaGetSymbolAddress((void**)&p_Gnd,   d_Gnd);

    const dim3 linGrid((B_ * NSEQ) / 64, CD / 64);

    // Stage 1: four linears
    lin_kernel<<<linGrid, 256>>>(detect, g_w,  g_b,  nullptr, p_g);
    lin_kernel<<<linGrid, 256>>>(aim,    g2_w, g2_b, nullptr, p_g2);
    lin_kernel<<<linGrid, 256>>>(aim,    th_w, th_b, nullptr, p_theta);
    lin_kernel<<<linGrid, 256>>>(detect, ph_w, ph_b, nullptr, p_phi);

    // Stage 2: permutes == per-batch (128,4096) -> (4096,128) transposes
    const dim3 tb(32, 8);
    const dim3 tg1(M2 / 32, ICH / 32, B_);
    transpose_kernel<<<tg1, tb>>>(p_theta, p_T, ICH, M2);
    transpose_kernel<<<tg1, tb>>>(p_phi,   p_P, ICH, M2);
    transpose_kernel<<<tg1, tb>>>(p_g,     p_D, ICH, M2);
    transpose_kernel<<<tg1, tb>>>(p_g2,    p_A, ICH, M2);

    // Stage 3: f = (T @ P^T) / 4096   (one scale serves both consumers)
    gemmf_kernel<<<dim3(M2 / 128, M2 / 128, B_), 256>>>();

    // Stage 4: na = f @ D (NN), nd = f^T @ A (TN, reads f with coalesced rows)
    gemm2_kernel<<<dim3(M2 / 64, 2, B_), 256>>>();

    // Stage 5: back-transposes (4096,128) -> (128,4096)
    const dim3 tg2(ICH / 32, M2 / 32, B_);
    transpose_kernel<<<tg2, tb>>>(p_na, p_Gna, M2, ICH);
    transpose_kernel<<<tg2, tb>>>(p_nd, p_Gnd, M2, ICH);

    // Stage 6: final linears + residuals, straight into d_out
    lin_kernel<<<linGrid, 256>>>(p_Gnd, Q_w, Q_b, detect, out_det);
    lin_kernel<<<linGrid, 256>>>(p_Gna, W_w, W_b, aim,    out_aim);
}

// round 2
// speedup vs baseline: 6.8086x; 6.8086x over previous
#include <cuda_runtime.h>
#include <cstddef>

#define B_    4
#define NSEQ  2048
#define CD    256
#define ICH   128
#define M2    4096                    // 2*NSEQ
#define LIN_ELEMS (B_*NSEQ*CD)        // 2,097,152 floats per tensor
#define BSTRIDE   (NSEQ*CD)           // 524,288 floats per batch
#define NSPLIT    32                  // split-K chunks for S1/S2 (K=4096 -> 128 each)

// Scratch (device globals; allocation is forbidden)
__device__ float d_g    [LIN_ELEMS];   // g(detect)   -> Gr (128,4096) per batch
__device__ float d_g2   [LIN_ELEMS];   // g2(aim)     -> A2
__device__ float d_theta[LIN_ELEMS];   // theta(aim)  -> Th
__device__ float d_phi  [LIN_ELEMS];   // phi(detect) -> Ph
__device__ float d_Spart[2*B_*NSPLIT*ICH*ICH];  // split-K partials (16.8M floats)
__device__ float d_S    [2*B_*ICH*ICH];         // S1/S2, pre-scaled by 1/4096
__device__ float d_naT  [LIN_ELEMS];
__device__ float d_ndT  [LIN_ELEMS];

// ---------------------------------------------------------------------------
// Fused front linears: z selects one of 4 (X, W, bias) -> Y.
// Y[M,256] = X[M,256] @ W^T + b.  128x128 tile, 256 thr, 8x8/thread, KT=16.
// grid = (8192/128=64, 256/128=2, 4)
// ---------------------------------------------------------------------------
__global__ __launch_bounds__(256) void lin4_kernel(
    const float* __restrict__ X0, const float* __restrict__ W0, const float* __restrict__ b0,
    const float* __restrict__ X1, const float* __restrict__ W1, const float* __restrict__ b1,
    const float* __restrict__ X2, const float* __restrict__ W2, const float* __restrict__ b2,
    const float* __restrict__ X3, const float* __restrict__ W3, const float* __restrict__ b3)
{
    __shared__ float As[16][128];
    __shared__ float Bs[16][128];
    const int z = blockIdx.z;
    const float* X; const float* W; const float* bias; float* Y;
    float *pg, *pg2, *pth, *pph;
    // device-side symbol addresses are direct
    pg = d_g; pg2 = d_g2; pth = d_theta; pph = d_phi;
    if      (z == 0) { X = X0; W = W0; bias = b0; Y = pg;  }
    else if (z == 1) { X = X1; W = W1; bias = b1; Y = pg2; }
    else if (z == 2) { X = X2; W = W2; bias = b2; Y = pth; }
    else             { X = X3; W = W3; bias = b3; Y = pph; }

    const int m0 = blockIdx.x * 128, n0 = blockIdx.y * 128;
    const int tid = threadIdx.x;
    const int tx = tid & 15, ty = tid >> 4;
    const int lm = tid >> 1, lk = (tid & 1) * 8;
    float acc[8][8] = {};

    for (int k0 = 0; k0 < CD; k0 += 16) {
        float4 a0 = *(const float4*)&X[(size_t)(m0 + lm) * CD + k0 + lk];
        float4 a1 = *(const float4*)&X[(size_t)(m0 + lm) * CD + k0 + lk + 4];
        float4 b0v = *(const float4*)&W[(size_t)(n0 + lm) * CD + k0 + lk];
        float4 b1v = *(const float4*)&W[(size_t)(n0 + lm) * CD + k0 + lk + 4];
        As[lk+0][lm]=a0.x; As[lk+1][lm]=a0.y; As[lk+2][lm]=a0.z; As[lk+3][lm]=a0.w;
        As[lk+4][lm]=a1.x; As[lk+5][lm]=a1.y; As[lk+6][lm]=a1.z; As[lk+7][lm]=a1.w;
        Bs[lk+0][lm]=b0v.x; Bs[lk+1][lm]=b0v.y; Bs[lk+2][lm]=b0v.z; Bs[lk+3][lm]=b0v.w;
        Bs[lk+4][lm]=b1v.x; Bs[lk+5][lm]=b1v.y; Bs[lk+6][lm]=b1v.z; Bs[lk+7][lm]=b1v.w;
        __syncthreads();
#pragma unroll
        for (int k = 0; k < 16; k++) {
            float a[8], b[8];
#pragma unroll
            for (int i = 0; i < 8; i++) { a[i] = As[k][ty*8+i]; b[i] = Bs[k][tx*8+i]; }
#pragma unroll
            for (int i = 0; i < 8; i++)
#pragma unroll
                for (int j = 0; j < 8; j++) acc[i][j] += a[i] * b[j];
        }
        __syncthreads();
    }
#pragma unroll
    for (int i = 0; i < 8; i++) {
        float* row = &Y[(size_t)(m0 + ty*8 + i) * CD + n0 + tx*8];
#pragma unroll
        for (int j = 0; j < 8; j++) row[j] = acc[i][j] + bias[n0 + tx*8 + j];
    }
}

// ---------------------------------------------------------------------------
// Split-K partials for S1/S2 (NT GEMM, M=N=128, K=4096 split by NSPLIT).
// type 0: S1 = Ph @ Gr^T ;  type 1: S2 = Th @ A2^T
// grid = (NSPLIT, 2, B_), block 256
// ---------------------------------------------------------------------------
__global__ __launch_bounds__(256) void s_partial_kernel()
{
    __shared__ float As[16][128];
    __shared__ float Bs[16][128];
    const int split = blockIdx.x, type = blockIdx.y, b = blockIdx.z;
    const float* A = (type ? d_theta : d_phi) + (size_t)b * BSTRIDE;  // (128,4096)
    const float* Bm = (type ? d_g2   : d_g  ) + (size_t)b * BSTRIDE;
    const int kbase = split * (M2 / NSPLIT);   // 128-wide chunk
    const int tid = threadIdx.x;
    const int tx = tid & 15, ty = tid >> 4;
    const int lm = tid >> 1, lk = (tid & 1) * 8;
    float acc[8][8] = {};

    for (int k0 = 0; k0 < M2 / NSPLIT; k0 += 16) {
        const int kk = kbase + k0 + lk;
        float4 a0 = *(const float4*)&A [(size_t)lm * M2 + kk];
        float4 a1 = *(const float4*)&A [(size_t)lm * M2 + kk + 4];
        float4 b0v = *(const float4*)&Bm[(size_t)lm * M2 + kk];
        float4 b1v = *(const float4*)&Bm[(size_t)lm * M2 + kk + 4];
        As[lk+0][lm]=a0.x; As[lk+1][lm]=a0.y; As[lk+2][lm]=a0.z; As[lk+3][lm]=a0.w;
        As[lk+4][lm]=a1.x; As[lk+5][lm]=a1.y; As[lk+6][lm]=a1.z; As[lk+7][lm]=a1.w;
        Bs[lk+0][lm]=b0v.x; Bs[lk+1][lm]=b0v.y; Bs[lk+2][lm]=b0v.z; Bs[lk+3][lm]=b0v.w;
        Bs[lk+4][lm]=b1v.x; Bs[lk+5][lm]=b1v.y; Bs[lk+6][lm]=b1v.z; Bs[lk+7][lm]=b1v.w;
        __syncthreads();
#pragma unroll
        for (int k = 0; k < 16; k++) {
            float a[8], b[8];
#pragma unroll
            for (int i = 0; i < 8; i++) { a[i] = As[k][ty*8+i]; b[i] = Bs[k][tx*8+i]; }
#pragma unroll
            for (int i = 0; i < 8; i++)
#pragma unroll
                for (int j = 0; j < 8; j++) acc[i][j] += a[i] * b[j];
        }
        __syncthreads();
    }
    float* out = d_Spart + ((size_t)((type * B_ + b) * NSPLIT + split)) * (ICH * ICH);
#pragma unroll
    for (int i = 0; i < 8; i++) {
        float* row = &out[(ty*8 + i) * ICH + tx*8];
#pragma unroll
        for (int j = 0; j < 8; j++) row[j] = acc[i][j];
    }
}

// ---------------------------------------------------------------------------
// Deterministic reduction of split-K partials, folds the 1/4096 scale.
// grid = (ICH*ICH/256 = 64, 2*B_), block 256
// ---------------------------------------------------------------------------
__global__ __launch_bounds__(256) void s_reduce_kernel()
{
    const int e = blockIdx.x * 256 + threadIdx.x;   // 0..16383
    const int mat = blockIdx.y;                     // 0..7
    const float* base = d_Spart + (size_t)mat * NSPLIT * (ICH * ICH) + e;
    float s = 0.0f;
#pragma unroll
    for (int sp = 0; sp < NSPLIT; sp++) s += base[(size_t)sp * (ICH * ICH)];
    d_S[(size_t)mat * (ICH * ICH) + e] = s * (1.0f / 4096.0f);
}

// ---------------------------------------------------------------------------
// naT/ndT: C[i,p] = sum_k S[k,i] * Tm[k,p].   (128 x 4096, K=128)
// type 0: S1s & Th -> naT ;  type 1: S2s & Ph -> ndT
// grid = (M2/128 = 32, 2, B_), block 256
// ---------------------------------------------------------------------------
__global__ __launch_bounds__(256) void out_small_kernel()
{
    __shared__ float Ss[16][128];
    __shared__ float Ts[16][128];
    const int p0 = blockIdx.x * 128, type = blockIdx.y, b = blockIdx.z;
    const float* S  = d_S + (size_t)(type * B_ + b) * (ICH * ICH);
    const float* Tm = (type ? d_phi : d_theta) + (size_t)b * BSTRIDE;   // (128,4096)
    float* Y = (type ? d_ndT : d_naT) + (size_t)b * BSTRIDE;
    const int tid = threadIdx.x;
    const int tx = tid & 15, ty = tid >> 4;
    const int lr = tid >> 4, lc = (tid & 15) * 8;   // 16 rows x 128 cols loads
    float acc[8][8] = {};

    for (int k0 = 0; k0 < ICH; k0 += 16) {
        float4 s0 = *(const float4*)&S [(size_t)(k0 + lr) * ICH + lc];
        float4 s1 = *(const float4*)&S [(size_t)(k0 + lr) * ICH + lc + 4];
        float4 t0 = *(const float4*)&Tm[(size_t)(k0 + lr) * M2 + p0 + lc];
        float4 t1 = *(const float4*)&Tm[(size_t)(k0 + lr) * M2 + p0 + lc + 4];
        Ss[lr][lc+0]=s0.x; Ss[lr][lc+1]=s0.y; Ss[lr][lc+2]=s0.z; Ss[lr][lc+3]=s0.w;
        Ss[lr][lc+4]=s1.x; Ss[lr][lc+5]=s1.y; Ss[lr][lc+6]=s1.z; Ss[lr][lc+7]=s1.w;
        Ts[lr][lc+0]=t0.x; Ts[lr][lc+1]=t0.y; Ts[lr][lc+2]=t0.z; Ts[lr][lc+3]=t0.w;
        Ts[lr][lc+4]=t1.x; Ts[lr][lc+5]=t1.y; Ts[lr][lc+6]=t1.z; Ts[lr][lc+7]=t1.w;
        __syncthreads();
#pragma unroll
        for (int k = 0; k < 16; k++) {
            float a[8], b[8];
#pragma unroll
            for (int i = 0; i < 8; i++) { a[i] = Ss[k][ty*8+i]; b[i] = Ts[k][tx*8+i]; }
#pragma unroll
            for (int i = 0; i < 8; i++)
#pragma unroll
                for (int j = 0; j < 8; j++) acc[i][j] += a[i] * b[j];
        }
        __syncthreads();
    }
#pragma unroll
    for (int i = 0; i < 8; i++) {
        float* row = &Y[(size_t)(ty*8 + i) * M2 + p0 + tx*8];
#pragma unroll
        for (int j = 0; j < 8; j++) row[j] = acc[i][j];
    }
}

// ---------------------------------------------------------------------------
// Fused final linears + residual. z=0: Q(ndT)+detect -> out_det
//                                 z=1: W(naT)+aim    -> out_aim
// grid = (64, 2, 2), block 256
// ---------------------------------------------------------------------------
__global__ __launch_bounds__(256) void lin2_kernel(
    const float* __restrict__ Qw, const float* __restrict__ Qb, const float* __restrict__ det,
    const float* __restrict__ Ww, const float* __restrict__ Wb, const float* __restrict__ aim,
    float* __restrict__ out_det, float* __restrict__ out_aim)
{
    __shared__ float As[16][128];
    __shared__ float Bs[16][128];
    const int z = blockIdx.z;
    const float* X = z ? d_naT : d_ndT;
    const float* W = z ? Ww : Qw;
    const float* bias = z ? Wb : Qb;
    const float* res  = z ? aim : det;
    float* Y = z ? out_aim : out_det;

    const int m0 = blockIdx.x * 128, n0 = blockIdx.y * 128;
    const int tid = threadIdx.x;
    const int tx = tid & 15, ty = tid >> 4;
    const int lm = tid >> 1, lk = (tid & 1) * 8;
    float acc[8][8] = {};

    for (int k0 = 0; k0 < CD; k0 += 16) {
        float4 a0 = *(const float4*)&X[(size_t)(m0 + lm) * CD + k0 + lk];
        float4 a1 = *(const float4*)&X[(size_t)(m0 + lm) * CD + k0 + lk + 4];
        float4 b0v = *(const float4*)&W[(size_t)(n0 + lm) * CD + k0 + lk];
        float4 b1v = *(const float4*)&W[(size_t)(n0 + lm) * CD + k0 + lk + 4];
        As[lk+0][lm]=a0.x; As[lk+1][lm]=a0.y; As[lk+2][lm]=a0.z; As[lk+3][lm]=a0.w;
        As[lk+4][lm]=a1.x; As[lk+5][lm]=a1.y; As[lk+6][lm]=a1.z; As[lk+7][lm]=a1.w;
        Bs[lk+0][lm]=b0v.x; Bs[lk+1][lm]=b0v.y; Bs[lk+2][lm]=b0v.z; Bs[lk+3][lm]=b0v.w;
        Bs[lk+4][lm]=b1v.x; Bs[lk+5][lm]=b1v.y; Bs[lk+6][lm]=b1v.z; Bs[lk+7][lm]=b1v.w;
        __syncthreads();
#pragma unroll
        for (int k = 0; k < 16; k++) {
            float a[8], b[8];
#pragma unroll
            for (int i = 0; i < 8; i++) { a[i] = As[k][ty*8+i]; b[i] = Bs[k][tx*8+i]; }
#pragma unroll
            for (int i = 0; i < 8; i++)
#pragma unroll
                for (int j = 0; j < 8; j++) acc[i][j] += a[i] * b[j];
        }
        __syncthreads();
    }
#pragma unroll
    for (int i = 0; i < 8; i++) {
        const int m = m0 + ty*8 + i;
        float* row = &Y[(size_t)m * CD + n0 + tx*8];
        const float* rrow = &res[(size_t)m * CD + n0 + tx*8];
#pragma unroll
        for (int j = 0; j < 8; j++) row[j] = acc[i][j] + bias[n0 + tx*8 + j] + rrow[j];
    }
}

// ---------------------------------------------------------------------------
extern "C" void kernel_launch(void* const* d_in, const int* in_sizes, int n_in,
                              void* d_out, int out_size)
{
    const float* detect = (const float*)d_in[0];
    const float* aim    = (const float*)d_in[1];
    const float* g_w  = (const float*)d_in[2];  const float* g_b  = (const float*)d_in[3];
    const float* g2_w = (const float*)d_in[4];  const float* g2_b = (const float*)d_in[5];
    const float* th_w = (const float*)d_in[6];  const float* th_b = (const float*)d_in[7];
    const float* ph_w = (const float*)d_in[8];  const float* ph_b = (const float*)d_in[9];
    const float* W_w  = (const float*)d_in[10]; const float* W_b  = (const float*)d_in[11];
    const float* Q_w  = (const float*)d_in[12]; const float* Q_b  = (const float*)d_in[13];

    float* out_det = (float*)d_out;                      // non_det first
    float* out_aim = out_det + (size_t)B_ * NSEQ * CD;   // then non_aim

    // Stage 1: four front linears (one fused launch)
    lin4_kernel<<<dim3(64, 2, 4), 256>>>(
        detect, g_w,  g_b,     // -> d_g
        aim,    g2_w, g2_b,    // -> d_g2
        aim,    th_w, th_b,    // -> d_theta
        detect, ph_w, ph_b);   // -> d_phi

    // Stage 2: S1 = Ph@Gr^T, S2 = Th@A2^T via split-K + deterministic reduce
    s_partial_kernel<<<dim3(NSPLIT, 2, B_), 256>>>();
    s_reduce_kernel<<<dim3(64, 2 * B_), 256>>>();

    // Stage 3: naT = S1s^T-contract with Th, ndT with Ph (128 x 4096 each)
    out_small_kernel<<<dim3(M2 / 128, 2, B_), 256>>>();

    // Stage 4: final linears + residuals straight into d_out
    lin2_kernel<<<dim3(64, 2, 2), 256>>>(
        Q_w, Q_b, detect, W_w, W_b, aim, out_det, out_aim);
}

// round 3
// speedup vs baseline: 8.0379x; 1.1806x over previous
#include <cuda_runtime.h>
#include <mma.h>
#include <cstddef>

using namespace nvcuda;

#define B_    4
#define NSEQ  2048
#define CD    256
#define ICH   128
#define M2    4096                    // 2*NSEQ
#define LIN_ELEMS (B_*NSEQ*CD)        // 2,097,152 floats
#define BSTRIDE   (NSEQ*CD)           // 524,288 floats per batch
#define NSPLIT    32                  // split-K for S1/S2 (K=4096 -> 128 each)

// Scratch (device globals; allocation forbidden)
__device__ float d_g    [LIN_ELEMS];   // g(detect)   -> Gr (128,4096)/batch
__device__ float d_g2   [LIN_ELEMS];   // g2(aim)     -> A2
__device__ float d_theta[LIN_ELEMS];   // theta(aim)  -> Th
__device__ float d_phi  [LIN_ELEMS];   // phi(detect) -> Ph
__device__ float d_Spart[2*B_*NSPLIT*ICH*ICH];
__device__ float d_S    [2*B_*ICH*ICH];            // pre-scaled by 1/4096
__device__ float d_naT  [LIN_ELEMS];
__device__ float d_ndT  [LIN_ELEMS];

#define FRAG_A_R wmma::fragment<wmma::matrix_a, 16, 16, 8, wmma::precision::tf32, wmma::row_major>
#define FRAG_A_C wmma::fragment<wmma::matrix_a, 16, 16, 8, wmma::precision::tf32, wmma::col_major>
#define FRAG_B_R wmma::fragment<wmma::matrix_b, 16, 16, 8, wmma::precision::tf32, wmma::row_major>
#define FRAG_B_C wmma::fragment<wmma::matrix_b, 16, 16, 8, wmma::precision::tf32, wmma::col_major>
#define FRAG_ACC wmma::fragment<wmma::accumulator, 16, 16, 8, float>

template <typename F>
__device__ __forceinline__ void cvt_tf32(F& f) {
#pragma unroll
    for (int t = 0; t < f.num_elements; t++) f.x[t] = wmma::__float_to_tf32(f.x[t]);
}

// ---------------------------------------------------------------------------
// Fused front linears: Y = X[8192,256] @ W[256,256]^T + bias.
// grid (64, 2, 4); block 256 = 8 warps (4 m-warps x 2 n-warps), warp 32x64.
// ---------------------------------------------------------------------------
__global__ __launch_bounds__(256) void lin4_tc(
    const float* __restrict__ X0, const float* __restrict__ W0, const float* __restrict__ b0,
    const float* __restrict__ X1, const float* __restrict__ W1, const float* __restrict__ b1,
    const float* __restrict__ X2, const float* __restrict__ W2, const float* __restrict__ b2,
    const float* __restrict__ X3, const float* __restrict__ W3, const float* __restrict__ b3)
{
    __shared__ float patch[8][16][20];
    const int z = blockIdx.z;
    const float* X; const float* W; const float* bias; float* Y;
    if      (z == 0) { X = X0; W = W0; bias = b0; Y = d_g;     }
    else if (z == 1) { X = X1; W = W1; bias = b1; Y = d_g2;    }
    else if (z == 2) { X = X2; W = W2; bias = b2; Y = d_theta; }
    else             { X = X3; W = W3; bias = b3; Y = d_phi;   }

    const int tid = threadIdx.x, wid = tid >> 5, lane = tid & 31;
    const int wm = wid & 3, wn = wid >> 2;
    const int mw = blockIdx.x * 128 + wm * 32;
    const int nw = blockIdx.y * 128 + wn * 64;

    FRAG_ACC acc[2][4];
#pragma unroll
    for (int i = 0; i < 2; i++)
#pragma unroll
        for (int j = 0; j < 4; j++) wmma::fill_fragment(acc[i][j], 0.0f);

    for (int k0 = 0; k0 < CD; k0 += 8) {
        FRAG_A_R a[2];
        FRAG_B_C b[4];
#pragma unroll
        for (int i = 0; i < 2; i++) {
            wmma::load_matrix_sync(a[i], X + (size_t)(mw + 16*i) * CD + k0, CD);
            cvt_tf32(a[i]);
        }
#pragma unroll
        for (int j = 0; j < 4; j++) {
            wmma::load_matrix_sync(b[j], W + (size_t)(nw + 16*j) * CD + k0, CD);
            cvt_tf32(b[j]);
        }
#pragma unroll
        for (int i = 0; i < 2; i++)
#pragma unroll
            for (int j = 0; j < 4; j++) wmma::mma_sync(acc[i][j], a[i], b[j], acc[i][j]);
    }
    // epilogue: + bias
    const int pr = lane & 15, pc = (lane >> 4) * 8;
#pragma unroll
    for (int i = 0; i < 2; i++)
#pragma unroll
        for (int j = 0; j < 4; j++) {
            wmma::store_matrix_sync(&patch[wid][0][0], acc[i][j], 20, wmma::mem_row_major);
            __syncwarp();
            const int m = mw + 16*i + pr;
            const int nb = nw + 16*j + pc;
            float* row = &Y[(size_t)m * CD + nb];
#pragma unroll
            for (int t = 0; t < 8; t++) row[t] = patch[wid][pr][pc + t] + bias[nb + t];
            __syncwarp();
        }
}

// ---------------------------------------------------------------------------
// Split-K partials: type 0: S1 = Ph @ Gr^T ; type 1: S2 = Th @ A2^T
// C is 128x128, K-chunk 128. grid (NSPLIT, 2, B_)
// ---------------------------------------------------------------------------
__global__ __launch_bounds__(256) void s_partial_tc()
{
    const int split = blockIdx.x, type = blockIdx.y, b = blockIdx.z;
    const float* A  = (type ? d_theta : d_phi) + (size_t)b * BSTRIDE;  // (128,4096)
    const float* Bm = (type ? d_g2   : d_g  ) + (size_t)b * BSTRIDE;
    const int kbase = split * (M2 / NSPLIT);
    const int wid = threadIdx.x >> 5;
    const int wm = wid & 3, wn = wid >> 2;
    const int mw = wm * 32, nw = wn * 64;

    FRAG_ACC acc[2][4];
#pragma unroll
    for (int i = 0; i < 2; i++)
#pragma unroll
        for (int j = 0; j < 4; j++) wmma::fill_fragment(acc[i][j], 0.0f);

    for (int k0 = 0; k0 < M2 / NSPLIT; k0 += 8) {
        FRAG_A_R a[2];
        FRAG_B_C bf[4];
#pragma unroll
        for (int i = 0; i < 2; i++) {
            wmma::load_matrix_sync(a[i], A + (size_t)(mw + 16*i) * M2 + kbase + k0, M2);
            cvt_tf32(a[i]);
        }
#pragma unroll
        for (int j = 0; j < 4; j++) {
            wmma::load_matrix_sync(bf[j], Bm + (size_t)(nw + 16*j) * M2 + kbase + k0, M2);
            cvt_tf32(bf[j]);
        }
#pragma unroll
        for (int i = 0; i < 2; i++)
#pragma unroll
            for (int j = 0; j < 4; j++) wmma::mma_sync(acc[i][j], a[i], bf[j], acc[i][j]);
    }
    float* out = d_Spart + ((size_t)((type * B_ + b) * NSPLIT + split)) * (ICH * ICH);
#pragma unroll
    for (int i = 0; i < 2; i++)
#pragma unroll
        for (int j = 0; j < 4; j++)
            wmma::store_matrix_sync(out + (size_t)(mw + 16*i) * ICH + nw + 16*j,
                                    acc[i][j], ICH, wmma::mem_row_major);
}

// ---------------------------------------------------------------------------
// Deterministic split-K reduce, folds 1/4096. grid (64, 2*B_), block 256
// ---------------------------------------------------------------------------
__global__ __launch_bounds__(256) void s_reduce_kernel()
{
    const int e = blockIdx.x * 256 + threadIdx.x;
    const int mat = blockIdx.y;
    const float* base = d_Spart + (size_t)mat * NSPLIT * (ICH * ICH) + e;
    float s = 0.0f;
#pragma unroll
    for (int sp = 0; sp < NSPLIT; sp++) s += base[(size_t)sp * (ICH * ICH)];
    d_S[(size_t)mat * (ICH * ICH) + e] = s * (1.0f / 4096.0f);
}

// ---------------------------------------------------------------------------
// C[i,p] = sum_k S[k,i] * Tm[k,p]  (S^T @ Tm). C tile 128 x 128 of (128,4096).
// type 0: S1,Th -> naT ; type 1: S2,Ph -> ndT.  grid (32, 2, B_)
// ---------------------------------------------------------------------------
__global__ __launch_bounds__(256) void out_small_tc()
{
    const int p0 = blockIdx.x * 128, type = blockIdx.y, b = blockIdx.z;
    const float* S  = d_S + (size_t)(type * B_ + b) * (ICH * ICH);
    const float* Tm = (type ? d_phi : d_theta) + (size_t)b * BSTRIDE;   // (128,4096)
    float* Y = (type ? d_ndT : d_naT) + (size_t)b * BSTRIDE;
    const int wid = threadIdx.x >> 5;
    const int wm = wid & 3, wn = wid >> 2;
    const int iw = wm * 32;            // i (row of C) offset
    const int pw = p0 + wn * 64;       // p (col of C) offset

    FRAG_ACC acc[2][4];
#pragma unroll
    for (int i = 0; i < 2; i++)
#pragma unroll
        for (int j = 0; j < 4; j++) wmma::fill_fragment(acc[i][j], 0.0f);

    for (int k0 = 0; k0 < ICH; k0 += 8) {
        FRAG_A_C a[2];                 // (i,k) = S[k*128 + i] -> col_major ld=128
        FRAG_B_R bf[4];                // (k,p) = Tm[k*M2 + p] -> row_major ld=M2
#pragma unroll
        for (int i = 0; i < 2; i++) {
            wmma::load_matrix_sync(a[i], S + (size_t)k0 * ICH + iw + 16*i, ICH);
            cvt_tf32(a[i]);
        }
#pragma unroll
        for (int j = 0; j < 4; j++) {
            wmma::load_matrix_sync(bf[j], Tm + (size_t)k0 * M2 + pw + 16*j, M2);
            cvt_tf32(bf[j]);
        }
#pragma unroll
        for (int i = 0; i < 2; i++)
#pragma unroll
            for (int j = 0; j < 4; j++) wmma::mma_sync(acc[i][j], a[i], bf[j], acc[i][j]);
    }
#pragma unroll
    for (int i = 0; i < 2; i++)
#pragma unroll
        for (int j = 0; j < 4; j++)
            wmma::store_matrix_sync(Y + (size_t)(iw + 16*i) * M2 + pw + 16*j,
                                    acc[i][j], M2, wmma::mem_row_major);
}

// ---------------------------------------------------------------------------
// Final linears + residual. z=0: Q(ndT)+detect -> out_det ; z=1: W(naT)+aim.
// grid (64, 2, 2)
// ---------------------------------------------------------------------------
__global__ __launch_bounds__(256) void lin2_tc(
    const float* __restrict__ Qw, const float* __restrict__ Qb, const float* __restrict__ det,
    const float* __restrict__ Ww, const float* __restrict__ Wb, const float* __restrict__ aim,
    float* __restrict__ out_det, float* __restrict__ out_aim)
{
    __shared__ float patch[8][16][20];
    const int z = blockIdx.z;
    const float* X = z ? d_naT : d_ndT;
    const float* W = z ? Ww : Qw;
    const float* bias = z ? Wb : Qb;
    const float* res  = z ? aim : det;
    float* Y = z ? out_aim : out_det;

    const int tid = threadIdx.x, wid = tid >> 5, lane = tid & 31;
    const int wm = wid & 3, wn = wid >> 2;
    const int mw = blockIdx.x * 128 + wm * 32;
    const int nw = blockIdx.y * 128 + wn * 64;

    FRAG_ACC acc[2][4];
#pragma unroll
    for (int i = 0; i < 2; i++)
#pragma unroll
        for (int j = 0; j < 4; j++) wmma::fill_fragment(acc[i][j], 0.0f);

    for (int k0 = 0; k0 < CD; k0 += 8) {
        FRAG_A_R a[2];
        FRAG_B_C b[4];
#pragma unroll
        for (int i = 0; i < 2; i++) {
            wmma::load_matrix_sync(a[i], X + (size_t)(mw + 16*i) * CD + k0, CD);
            cvt_tf32(a[i]);
        }
#pragma unroll
        for (int j = 0; j < 4; j++) {
            wmma::load_matrix_sync(b[j], W + (size_t)(nw + 16*j) * CD + k0, CD);
            cvt_tf32(b[j]);
        }
#pragma unroll
        for (int i = 0; i < 2; i++)
#pragma unroll
            for (int j = 0; j < 4; j++) wmma::mma_sync(acc[i][j], a[i], b[j], acc[i][j]);
    }
    const int pr = lane & 15, pc = (lane >> 4) * 8;
#pragma unroll
    for (int i = 0; i < 2; i++)
#pragma unroll
        for (int j = 0; j < 4; j++) {
            wmma::store_matrix_sync(&patch[wid][0][0], acc[i][j], 20, wmma::mem_row_major);
            __syncwarp();
            const int m = mw + 16*i + pr;
            const int nb = nw + 16*j + pc;
            float* row = &Y[(size_t)m * CD + nb];
            const float* rrow = &res[(size_t)m * CD + nb];
#pragma unroll
            for (int t = 0; t < 8; t++)
                row[t] = patch[wid][pr][pc + t] + bias[nb + t] + rrow[t];
            __syncwarp();
        }
}

// ---------------------------------------------------------------------------
extern "C" void kernel_launch(void* const* d_in, const int* in_sizes, int n_in,
                              void* d_out, int out_size)
{
    const float* detect = (const float*)d_in[0];
    const float* aim    = (const float*)d_in[1];
    const float* g_w  = (const float*)d_in[2];  const float* g_b  = (const float*)d_in[3];
    const float* g2_w = (const float*)d_in[4];  const float* g2_b = (const float*)d_in[5];
    const float* th_w = (const float*)d_in[6];  const float* th_b = (const float*)d_in[7];
    const float* ph_w = (const float*)d_in[8];  const float* ph_b = (const float*)d_in[9];
    const float* W_w  = (const float*)d_in[10]; const float* W_b  = (const float*)d_in[11];
    const float* Q_w  = (const float*)d_in[12]; const float* Q_b  = (const float*)d_in[13];

    float* out_det = (float*)d_out;                      // non_det first
    float* out_aim = out_det + (size_t)B_ * NSEQ * CD;   // then non_aim

    lin4_tc<<<dim3(64, 2, 4), 256>>>(
        detect, g_w,  g_b,
        aim,    g2_w, g2_b,
        aim,    th_w, th_b,
        detect, ph_w, ph_b);

    s_partial_tc<<<dim3(NSPLIT, 2, B_), 256>>>();
    s_reduce_kernel<<<dim3(64, 2 * B_), 256>>>();

    out_small_tc<<<dim3(M2 / 128, 2, B_), 256>>>();

    lin2_tc<<<dim3(64, 2, 2), 256>>>(
        Q_w, Q_b, detect, W_w, W_b, aim, out_det, out_aim);
}

// round 4
// speedup vs baseline: 10.1167x; 1.2586x over previous
#include <cuda_runtime.h>
#include <mma.h>
#include <cstddef>
#include <cstdint>

using namespace nvcuda;

#define B_    4
#define NSEQ  2048
#define CD    256
#define ICH   128
#define M2    4096                    // 2*NSEQ
#define LIN_ELEMS (B_*NSEQ*CD)        // 2,097,152 floats
#define BSTRIDE   (NSEQ*CD)           // 524,288 floats per batch
#define NSPLIT    16                  // split-K for S1/S2 (K=4096 -> 256 each)

// Scratch (device globals; allocation forbidden)
__device__ float d_g    [LIN_ELEMS];
__device__ float d_g2   [LIN_ELEMS];
__device__ float d_theta[LIN_ELEMS];
__device__ float d_phi  [LIN_ELEMS];
__device__ float d_Spart[2*B_*NSPLIT*ICH*ICH];   // 8 MB
__device__ float d_S    [2*B_*ICH*ICH];
__device__ float d_naT  [LIN_ELEMS];
__device__ float d_ndT  [LIN_ELEMS];

#define FRAG_A_R wmma::fragment<wmma::matrix_a, 16, 16, 8, wmma::precision::tf32, wmma::row_major>
#define FRAG_A_C wmma::fragment<wmma::matrix_a, 16, 16, 8, wmma::precision::tf32, wmma::col_major>
#define FRAG_B_R wmma::fragment<wmma::matrix_b, 16, 16, 8, wmma::precision::tf32, wmma::row_major>
#define FRAG_B_C wmma::fragment<wmma::matrix_b, 16, 16, 8, wmma::precision::tf32, wmma::col_major>
#define FRAG_ACC wmma::fragment<wmma::accumulator, 16, 16, 8, float>

template <typename F>
__device__ __forceinline__ void cvt_tf32(F& f) {
#pragma unroll
    for (int t = 0; t < f.num_elements; t++) f.x[t] = wmma::__float_to_tf32(f.x[t]);
}

// ---- cp.async helpers -----------------------------------------------------
__device__ __forceinline__ void cp16(float* s, const float* g) {
    uint32_t sa = (uint32_t)__cvta_generic_to_shared(s);
    asm volatile("cp.async.cg.shared.global [%0], [%1], 16;\n" :: "r"(sa), "l"(g));
}
__device__ __forceinline__ void cp_commit() { asm volatile("cp.async.commit_group;\n"); }
template <int N>
__device__ __forceinline__ void cp_wait() { asm volatile("cp.async.wait_group %0;\n" :: "n"(N)); }

// Row-slab staging: [128 rows][36 (=32 K + pad)]
#define LDS_PAD 36
#define SLAB    (128*LDS_PAD)
// K-slab staging (out_small): [32 K][132 (=128 + pad)]
#define LDS2    132
#define SLAB2   (32*LDS2)

// 256 threads copy a 128x32 fp32 tile (rows from gmem, ld = ldg)
__device__ __forceinline__ void load_slab36(float* dst, const float* src, size_t ldg,
                                            int k0, int t)
{
    const int row = t >> 1, c0 = (t & 1) * 16;
    const float* g = src + (size_t)row * ldg + k0 + c0;
    float* s = dst + row * LDS_PAD + c0;
    cp16(s, g); cp16(s + 4, g + 4); cp16(s + 8, g + 8); cp16(s + 12, g + 12);
}

// 256 threads copy a 32x128 fp32 tile (K-major rows), ld = ldg
__device__ __forceinline__ void load_slab132(float* dst, const float* src, size_t ldg,
                                             int k0, int t)
{
    const int kk = t >> 3, c0 = (t & 7) * 16;
    const float* g = src + (size_t)(k0 + kk) * ldg + c0;
    float* s = dst + kk * LDS2 + c0;
    cp16(s, g); cp16(s + 4, g + 4); cp16(s + 8, g + 8); cp16(s + 12, g + 12);
}

// Shared mainloop: C[128x128] += A(rowslab) x B(rowslab)^T, K = NT*32.
// As/Bs are double-buffered SLAB regions. mwl/nwl = warp-local tile offsets.
__device__ __forceinline__ void gemm_rowslab_mainloop(
    const float* Xt, size_t ldx, const float* Wt, size_t ldw, int NT,
    float* As, float* Bs, FRAG_ACC (&acc)[2][4], int tid, int mwl, int nwl)
{
    load_slab36(As, Xt, ldx, 0, tid);
    load_slab36(Bs, Wt, ldw, 0, tid);
    cp_commit();
    for (int kt = 0; kt < NT; kt++) {
        const int cur = kt & 1;
        if (kt + 1 < NT) {
            load_slab36(As + ((kt + 1) & 1) * SLAB, Xt, ldx, (kt + 1) * 32, tid);
            load_slab36(Bs + ((kt + 1) & 1) * SLAB, Wt, ldw, (kt + 1) * 32, tid);
            cp_commit();
            cp_wait<1>();
        } else {
            cp_wait<0>();
        }
        __syncthreads();
        const float* Ab = As + cur * SLAB;
        const float* Bb = Bs + cur * SLAB;
#pragma unroll
        for (int ks = 0; ks < 4; ks++) {
            const int kk = ks * 8;
            FRAG_A_R a[2];
            FRAG_B_C b[4];
#pragma unroll
            for (int i = 0; i < 2; i++) {
                wmma::load_matrix_sync(a[i], Ab + (mwl + 16 * i) * LDS_PAD + kk, LDS_PAD);
                cvt_tf32(a[i]);
            }
#pragma unroll
            for (int j = 0; j < 4; j++) {
                wmma::load_matrix_sync(b[j], Bb + (nwl + 16 * j) * LDS_PAD + kk, LDS_PAD);
                cvt_tf32(b[j]);
            }
#pragma unroll
            for (int i = 0; i < 2; i++)
#pragma unroll
                for (int j = 0; j < 4; j++) wmma::mma_sync(acc[i][j], a[i], b[j], acc[i][j]);
        }
        __syncthreads();
    }
}

// ---------------------------------------------------------------------------
// Front linears: Y = X[8192,256] @ W[256,256]^T + bias.  grid (64,2,4)
// ---------------------------------------------------------------------------
__global__ __launch_bounds__(256) void lin4_tc(
    const float* __restrict__ X0, const float* __restrict__ W0, const float* __restrict__ b0,
    const float* __restrict__ X1, const float* __restrict__ W1, const float* __restrict__ b1,
    const float* __restrict__ X2, const float* __restrict__ W2, const float* __restrict__ b2,
    const float* __restrict__ X3, const float* __restrict__ W3, const float* __restrict__ b3)
{
    extern __shared__ float smem[];
    __shared__ float patch[8][16][20];
    const int z = blockIdx.z;
    const float* X; const float* W; const float* bias; float* Y;
    if      (z == 0) { X = X0; W = W0; bias = b0; Y = d_g;     }
    else if (z == 1) { X = X1; W = W1; bias = b1; Y = d_g2;    }
    else if (z == 2) { X = X2; W = W2; bias = b2; Y = d_theta; }
    else             { X = X3; W = W3; bias = b3; Y = d_phi;   }

    const int tid = threadIdx.x, wid = tid >> 5, lane = tid & 31;
    const int wm = wid & 3, wn = wid >> 2;

    FRAG_ACC acc[2][4];
#pragma unroll
    for (int i = 0; i < 2; i++)
#pragma unroll
        for (int j = 0; j < 4; j++) wmma::fill_fragment(acc[i][j], 0.0f);

    const float* Xt = X + (size_t)(blockIdx.x * 128) * CD;
    const float* Wt = W + (size_t)(blockIdx.y * 128) * CD;
    gemm_rowslab_mainloop(Xt, CD, Wt, CD, CD / 32, smem, smem + 2 * SLAB,
                          acc, tid, wm * 32, wn * 64);

    const int m0 = blockIdx.x * 128 + wm * 32;
    const int n0 = blockIdx.y * 128 + wn * 64;
    const int pr = lane & 15, pc = (lane >> 4) * 8;
#pragma unroll
    for (int i = 0; i < 2; i++)
#pragma unroll
        for (int j = 0; j < 4; j++) {
            wmma::store_matrix_sync(&patch[wid][0][0], acc[i][j], 20, wmma::mem_row_major);
            __syncwarp();
            const int m = m0 + 16 * i + pr;
            const int nb = n0 + 16 * j + pc;
            float r[8];
#pragma unroll
            for (int t = 0; t < 8; t++) r[t] = patch[wid][pr][pc + t] + bias[nb + t];
            float* row = &Y[(size_t)m * CD + nb];
            *(float4*)(row)     = make_float4(r[0], r[1], r[2], r[3]);
            *(float4*)(row + 4) = make_float4(r[4], r[5], r[6], r[7]);
            __syncwarp();
        }
}

// ---------------------------------------------------------------------------
// Split-K partials: type 0: S1 = Ph @ Gr^T ; type 1: S2 = Th @ A2^T
// grid (NSPLIT, 2, B_); K-chunk = 256 per block
// ---------------------------------------------------------------------------
__global__ __launch_bounds__(256) void s_partial_tc()
{
    extern __shared__ float smem[];
    const int split = blockIdx.x, type = blockIdx.y, b = blockIdx.z;
    const float* A  = (type ? d_theta : d_phi) + (size_t)b * BSTRIDE;
    const float* Bm = (type ? d_g2   : d_g  ) + (size_t)b * BSTRIDE;
    const int kbase = split * (M2 / NSPLIT);
    const int tid = threadIdx.x, wid = tid >> 5;
    const int wm = wid & 3, wn = wid >> 2;

    FRAG_ACC acc[2][4];
#pragma unroll
    for (int i = 0; i < 2; i++)
#pragma unroll
        for (int j = 0; j < 4; j++) wmma::fill_fragment(acc[i][j], 0.0f);

    gemm_rowslab_mainloop(A + kbase, M2, Bm + kbase, M2, (M2 / NSPLIT) / 32,
                          smem, smem + 2 * SLAB, acc, tid, wm * 32, wn * 64);

    float* out = d_Spart + ((size_t)((type * B_ + b) * NSPLIT + split)) * (ICH * ICH);
#pragma unroll
    for (int i = 0; i < 2; i++)
#pragma unroll
        for (int j = 0; j < 4; j++)
            wmma::store_matrix_sync(out + (size_t)(wm * 32 + 16 * i) * ICH + wn * 64 + 16 * j,
                                    acc[i][j], ICH, wmma::mem_row_major);
}

// ---------------------------------------------------------------------------
// Deterministic split-K reduce, folds 1/4096. grid (64, 2*B_), block 256
// ---------------------------------------------------------------------------
__global__ __launch_bounds__(256) void s_reduce_kernel()
{
    const int e = blockIdx.x * 256 + threadIdx.x;
    const int mat = blockIdx.y;
    const float* base = d_Spart + (size_t)mat * NSPLIT * (ICH * ICH) + e;
    float s = 0.0f;
#pragma unroll
    for (int sp = 0; sp < NSPLIT; sp++) s += base[(size_t)sp * (ICH * ICH)];
    d_S[(size_t)mat * (ICH * ICH) + e] = s * (1.0f / 4096.0f);
}

// ---------------------------------------------------------------------------
// C[i,p] = sum_k S[k,i] * Tm[k,p]  (S^T @ Tm), tile 128x128 of (128,4096).
// grid (32, 2, B_); K = 128 (4 pipelined 32-slabs), conflict-free K-major smem.
// ---------------------------------------------------------------------------
__global__ __launch_bounds__(256) void out_small_tc()
{
    extern __shared__ float smem[];     // Ss[2][32][132] | Ts[2][32][132]
    float* Ss = smem;
    float* Ts = smem + 2 * SLAB2;
    const int p0 = blockIdx.x * 128, type = blockIdx.y, b = blockIdx.z;
    const float* S  = d_S + (size_t)(type * B_ + b) * (ICH * ICH);
    const float* Tm = (type ? d_phi : d_theta) + (size_t)b * BSTRIDE;
    float* Y = (type ? d_ndT : d_naT) + (size_t)b * BSTRIDE;
    const int tid = threadIdx.x, wid = tid >> 5;
    const int wm = wid & 3, wn = wid >> 2;
    const int iw = wm * 32, pwl = wn * 64;

    FRAG_ACC acc[2][4];
#pragma unroll
    for (int i = 0; i < 2; i++)
#pragma unroll
        for (int j = 0; j < 4; j++) wmma::fill_fragment(acc[i][j], 0.0f);

    load_slab132(Ss, S, ICH, 0, tid);
    load_slab132(Ts, Tm + p0, M2, 0, tid);
    cp_commit();
    const int NT = ICH / 32;            // 4
    for (int kt = 0; kt < NT; kt++) {
        const int cur = kt & 1;
        if (kt + 1 < NT) {
            load_slab132(Ss + ((kt + 1) & 1) * SLAB2, S, ICH, (kt + 1) * 32, tid);
            load_slab132(Ts + ((kt + 1) & 1) * SLAB2, Tm + p0, M2, (kt + 1) * 32, tid);
            cp_commit();
            cp_wait<1>();
        } else {
            cp_wait<0>();
        }
        __syncthreads();
        const float* Sb = Ss + cur * SLAB2;
        const float* Tb = Ts + cur * SLAB2;
#pragma unroll
        for (int ks = 0; ks < 4; ks++) {
            const int kk = ks * 8;
            FRAG_A_C a[2];              // (i,k) at Sb[kk*132 + i]
            FRAG_B_R bf[4];             // (k,p) at Tb[kk*132 + p]
#pragma unroll
            for (int i = 0; i < 2; i++) {
                wmma::load_matrix_sync(a[i], Sb + kk * LDS2 + iw + 16 * i, LDS2);
                cvt_tf32(a[i]);
            }
#pragma unroll
            for (int j = 0; j < 4; j++) {
                wmma::load_matrix_sync(bf[j], Tb + kk * LDS2 + pwl + 16 * j, LDS2);
                cvt_tf32(bf[j]);
            }
#pragma unroll
            for (int i = 0; i < 2; i++)
#pragma unroll
                for (int j = 0; j < 4; j++) wmma::mma_sync(acc[i][j], a[i], bf[j], acc[i][j]);
        }
        __syncthreads();
    }
#pragma unroll
    for (int i = 0; i < 2; i++)
#pragma unroll
        for (int j = 0; j < 4; j++)
            wmma::store_matrix_sync(Y + (size_t)(iw + 16 * i) * M2 + p0 + pwl + 16 * j,
                                    acc[i][j], M2, wmma::mem_row_major);
}

// ---------------------------------------------------------------------------
// Final linears + residual. z=0: Q(ndT)+detect -> out_det ; z=1: W(naT)+aim.
// grid (64, 2, 2)
// ---------------------------------------------------------------------------
__global__ __launch_bounds__(256) void lin2_tc(
    const float* __restrict__ Qw, const float* __restrict__ Qb, const float* __restrict__ det,
    const float* __restrict__ Ww, const float* __restrict__ Wb, const float* __restrict__ aim,
    float* __restrict__ out_det, float* __restrict__ out_aim)
{
    extern __shared__ float smem[];
    __shared__ float patch[8][16][20];
    const int z = blockIdx.z;
    const float* X = z ? d_naT : d_ndT;
    const float* W = z ? Ww : Qw;
    const float* bias = z ? Wb : Qb;
    const float* res  = z ? aim : det;
    float* Y = z ? out_aim : out_det;

    const int tid = threadIdx.x, wid = tid >> 5, lane = tid & 31;
    const int wm = wid & 3, wn = wid >> 2;

    FRAG_ACC acc[2][4];
#pragma unroll
    for (int i = 0; i < 2; i++)
#pragma unroll
        for (int j = 0; j < 4; j++) wmma::fill_fragment(acc[i][j], 0.0f);

    const float* Xt = X + (size_t)(blockIdx.x * 128) * CD;
    const float* Wt = W + (size_t)(blockIdx.y * 128) * CD;
    gemm_rowslab_mainloop(Xt, CD, Wt, CD, CD / 32, smem, smem + 2 * SLAB,
                          acc, tid, wm * 32, wn * 64);

    const int m0 = blockIdx.x * 128 + wm * 32;
    const int n0 = blockIdx.y * 128 + wn * 64;
    const int pr = lane & 15, pc = (lane >> 4) * 8;
#pragma unroll
    for (int i = 0; i < 2; i++)
#pragma unroll
        for (int j = 0; j < 4; j++) {
            wmma::store_matrix_sync(&patch[wid][0][0], acc[i][j], 20, wmma::mem_row_major);
            __syncwarp();
            const int m = m0 + 16 * i + pr;
            const int nb = n0 + 16 * j + pc;
            const float* rrow = &res[(size_t)m * CD + nb];
            float r[8];
#pragma unroll
            for (int t = 0; t < 8; t++)
                r[t] = patch[wid][pr][pc + t] + bias[nb + t] + rrow[t];
            float* row = &Y[(size_t)m * CD + nb];
            *(float4*)(row)     = make_float4(r[0], r[1], r[2], r[3]);
            *(float4*)(row + 4) = make_float4(r[4], r[5], r[6], r[7]);
            __syncwarp();
        }
}

// ---------------------------------------------------------------------------
extern "C" void kernel_launch(void* const* d_in, const int* in_sizes, int n_in,
                              void* d_out, int out_size)
{
    const float* detect = (const float*)d_in[0];
    const float* aim    = (const float*)d_in[1];
    const float* g_w  = (const float*)d_in[2];  const float* g_b  = (const float*)d_in[3];
    const float* g2_w = (const float*)d_in[4];  const float* g2_b = (const float*)d_in[5];
    const float* th_w = (const float*)d_in[6];  const float* th_b = (const float*)d_in[7];
    const float* ph_w = (const float*)d_in[8];  const float* ph_b = (const float*)d_in[9];
    const float* W_w  = (const float*)d_in[10]; const float* W_b  = (const float*)d_in[11];
    const float* Q_w  = (const float*)d_in[12]; const float* Q_b  = (const float*)d_in[13];

    float* out_det = (float*)d_out;
    float* out_aim = out_det + (size_t)B_ * NSEQ * CD;

    const int smemLin = 4 * SLAB * (int)sizeof(float);     // 73728
    const int smemOut = 4 * SLAB2 * (int)sizeof(float);    // 67584
    cudaFuncSetAttribute(lin4_tc,      cudaFuncAttributeMaxDynamicSharedMemorySize, smemLin);
    cudaFuncSetAttribute(s_partial_tc, cudaFuncAttributeMaxDynamicSharedMemorySize, smemLin);
    cudaFuncSetAttribute(out_small_tc, cudaFuncAttributeMaxDynamicSharedMemorySize, smemOut);
    cudaFuncSetAttribute(lin2_tc,      cudaFuncAttributeMaxDynamicSharedMemorySize, smemLin);

    lin4_tc<<<dim3(64, 2, 4), 256, smemLin>>>(
        detect, g_w,  g_b,
        aim,    g2_w, g2_b,
        aim,    th_w, th_b,
        detect, ph_w, ph_b);

    s_partial_tc<<<dim3(NSPLIT, 2, B_), 256, smemLin>>>();
    s_reduce_kernel<<<dim3(64, 2 * B_), 256>>>();

    out_small_tc<<<dim3(M2 / 128, 2, B_), 256, smemOut>>>();

    lin2_tc<<<dim3(64, 2, 2), 256, smemLin>>>(
        Q_w, Q_b, detect, W_w, W_b, aim, out_det, out_aim);
}

// round 5
// speedup vs baseline: 10.3839x; 1.0264x over previous
#include <cuda_runtime.h>
#include <mma.h>
#include <cstddef>
#include <cstdint>

using namespace nvcuda;

#define B_    4
#define NSEQ  2048
#define CD    256
#define ICH   128
#define M2    4096                    // 2*NSEQ
#define LIN_ELEMS (B_*NSEQ*CD)        // 2,097,152 floats
#define BSTRIDE   (NSEQ*CD)           // 524,288 floats per batch
#define NSPLIT    16                  // split-K for S1/S2 (K=4096 -> 256 each)

// Scratch (device globals; allocation forbidden)
__device__ float d_g    [LIN_ELEMS];
__device__ float d_g2   [LIN_ELEMS];
__device__ float d_theta[LIN_ELEMS];
__device__ float d_phi  [LIN_ELEMS];
__device__ float d_Spart[2*B_*NSPLIT*ICH*ICH];   // 8 MB
__device__ float d_S    [2*B_*ICH*ICH];
__device__ float d_naT  [LIN_ELEMS];
__device__ float d_ndT  [LIN_ELEMS];

#define FRAG_A_R wmma::fragment<wmma::matrix_a, 16, 16, 8, wmma::precision::tf32, wmma::row_major>
#define FRAG_A_C wmma::fragment<wmma::matrix_a, 16, 16, 8, wmma::precision::tf32, wmma::col_major>
#define FRAG_B_R wmma::fragment<wmma::matrix_b, 16, 16, 8, wmma::precision::tf32, wmma::row_major>
#define FRAG_B_C wmma::fragment<wmma::matrix_b, 16, 16, 8, wmma::precision::tf32, wmma::col_major>
#define FRAG_ACC wmma::fragment<wmma::accumulator, 16, 16, 8, float>

template <typename F>
__device__ __forceinline__ void cvt_tf32(F& f) {
#pragma unroll
    for (int t = 0; t < f.num_elements; t++) f.x[t] = wmma::__float_to_tf32(f.x[t]);
}

// ---- cp.async helpers -----------------------------------------------------
__device__ __forceinline__ void cp16(float* s, const float* g) {
    uint32_t sa = (uint32_t)__cvta_generic_to_shared(s);
    asm volatile("cp.async.cg.shared.global [%0], [%1], 16;\n" :: "r"(sa), "l"(g));
}
__device__ __forceinline__ void cp_commit() { asm volatile("cp.async.commit_group;\n"); }
template <int N>
__device__ __forceinline__ void cp_wait() { asm volatile("cp.async.wait_group %0;\n" :: "n"(N)); }

// Row-slab staging: [128 rows][36 (=32 K + pad)]
#define LDS_PAD 36
#define SLAB    (128*LDS_PAD)
// K-slab staging (out_small): [32 K][132 (=128 + pad)]
#define LDS2    132
#define SLAB2   (32*LDS2)

// 256 threads copy a 128x32 fp32 tile (rows from gmem, ld = ldg)
__device__ __forceinline__ void load_slab36(float* dst, const float* src, size_t ldg,
                                            int k0, int t)
{
    const int row = t >> 1, c0 = (t & 1) * 16;
    const float* g = src + (size_t)row * ldg + k0 + c0;
    float* s = dst + row * LDS_PAD + c0;
    cp16(s, g); cp16(s + 4, g + 4); cp16(s + 8, g + 8); cp16(s + 12, g + 12);
}

// 256 threads copy a 32x128 fp32 tile (K-major rows), ld = ldg
__device__ __forceinline__ void load_slab132(float* dst, const float* src, size_t ldg,
                                             int k0, int t)
{
    const int kk = t >> 3, c0 = (t & 7) * 16;
    const float* g = src + (size_t)(k0 + kk) * ldg + c0;
    float* s = dst + kk * LDS2 + c0;
    cp16(s, g); cp16(s + 4, g + 4); cp16(s + 8, g + 8); cp16(s + 12, g + 12);
}

// Shared mainloop: C[128x128] += A(rowslab) x B(rowslab)^T, K = NT*32.
__device__ __forceinline__ void gemm_rowslab_mainloop(
    const float* Xt, size_t ldx, const float* Wt, size_t ldw, int NT,
    float* As, float* Bs, FRAG_ACC (&acc)[2][4], int tid, int mwl, int nwl)
{
    load_slab36(As, Xt, ldx, 0, tid);
    load_slab36(Bs, Wt, ldw, 0, tid);
    cp_commit();
    for (int kt = 0; kt < NT; kt++) {
        const int cur = kt & 1;
        if (kt + 1 < NT) {
            load_slab36(As + ((kt + 1) & 1) * SLAB, Xt, ldx, (kt + 1) * 32, tid);
            load_slab36(Bs + ((kt + 1) & 1) * SLAB, Wt, ldw, (kt + 1) * 32, tid);
            cp_commit();
            cp_wait<1>();
        } else {
            cp_wait<0>();
        }
        __syncthreads();
        const float* Ab = As + cur * SLAB;
        const float* Bb = Bs + cur * SLAB;
#pragma unroll
        for (int ks = 0; ks < 4; ks++) {
            const int kk = ks * 8;
            FRAG_A_R a[2];
            FRAG_B_C b[4];
#pragma unroll
            for (int i = 0; i < 2; i++) {
                wmma::load_matrix_sync(a[i], Ab + (mwl + 16 * i) * LDS_PAD + kk, LDS_PAD);
                cvt_tf32(a[i]);
            }
#pragma unroll
            for (int j = 0; j < 4; j++) {
                wmma::load_matrix_sync(b[j], Bb + (nwl + 16 * j) * LDS_PAD + kk, LDS_PAD);
                cvt_tf32(b[j]);
            }
#pragma unroll
            for (int i = 0; i < 2; i++)
#pragma unroll
                for (int j = 0; j < 4; j++) wmma::mma_sync(acc[i][j], a[i], b[j], acc[i][j]);
        }
        __syncthreads();
    }
}

// ---------------------------------------------------------------------------
// Front linears: Y = X[8192,256] @ W[256,256]^T + bias.  grid (64,2,4)
// ---------------------------------------------------------------------------
__global__ __launch_bounds__(256, 2) void lin4_tc(
    const float* __restrict__ X0, const float* __restrict__ W0, const float* __restrict__ b0,
    const float* __restrict__ X1, const float* __restrict__ W1, const float* __restrict__ b1,
    const float* __restrict__ X2, const float* __restrict__ W2, const float* __restrict__ b2,
    const float* __restrict__ X3, const float* __restrict__ W3, const float* __restrict__ b3)
{
    extern __shared__ float smem[];
    __shared__ float patch[8][16][20];
    const int z = blockIdx.z;
    const float* X; const float* W; const float* bias; float* Y;
    if      (z == 0) { X = X0; W = W0; bias = b0; Y = d_g;     }
    else if (z == 1) { X = X1; W = W1; bias = b1; Y = d_g2;    }
    else if (z == 2) { X = X2; W = W2; bias = b2; Y = d_theta; }
    else             { X = X3; W = W3; bias = b3; Y = d_phi;   }

    const int tid = threadIdx.x, wid = tid >> 5, lane = tid & 31;
    const int wm = wid & 3, wn = wid >> 2;

    FRAG_ACC acc[2][4];
#pragma unroll
    for (int i = 0; i < 2; i++)
#pragma unroll
        for (int j = 0; j < 4; j++) wmma::fill_fragment(acc[i][j], 0.0f);

    const float* Xt = X + (size_t)(blockIdx.x * 128) * CD;
    const float* Wt = W + (size_t)(blockIdx.y * 128) * CD;
    gemm_rowslab_mainloop(Xt, CD, Wt, CD, CD / 32, smem, smem + 2 * SLAB,
                          acc, tid, wm * 32, wn * 64);

    const int m0 = blockIdx.x * 128 + wm * 32;
    const int n0 = blockIdx.y * 128 + wn * 64;
    const int pr = lane & 15, pc = (lane >> 4) * 8;
#pragma unroll
    for (int i = 0; i < 2; i++)
#pragma unroll
        for (int j = 0; j < 4; j++) {
            wmma::store_matrix_sync(&patch[wid][0][0], acc[i][j], 20, wmma::mem_row_major);
            __syncwarp();
            const int m = m0 + 16 * i + pr;
            const int nb = n0 + 16 * j + pc;
            float r[8];
#pragma unroll
            for (int t = 0; t < 8; t++) r[t] = patch[wid][pr][pc + t] + bias[nb + t];
            float* row = &Y[(size_t)m * CD + nb];
            *(float4*)(row)     = make_float4(r[0], r[1], r[2], r[3]);
            *(float4*)(row + 4) = make_float4(r[4], r[5], r[6], r[7]);
            __syncwarp();
        }
}

// ---------------------------------------------------------------------------
// Split-K partials: type 0: S1 = Ph @ Gr^T ; type 1: S2 = Th @ A2^T
// grid (NSPLIT, 2, B_); K-chunk = 256 per block
// ---------------------------------------------------------------------------
__global__ __launch_bounds__(256, 2) void s_partial_tc()
{
    extern __shared__ float smem[];
    const int split = blockIdx.x, type = blockIdx.y, b = blockIdx.z;
    const float* A  = (type ? d_theta : d_phi) + (size_t)b * BSTRIDE;
    const float* Bm = (type ? d_g2   : d_g  ) + (size_t)b * BSTRIDE;
    const int kbase = split * (M2 / NSPLIT);
    const int tid = threadIdx.x, wid = tid >> 5;
    const int wm = wid & 3, wn = wid >> 2;

    FRAG_ACC acc[2][4];
#pragma unroll
    for (int i = 0; i < 2; i++)
#pragma unroll
        for (int j = 0; j < 4; j++) wmma::fill_fragment(acc[i][j], 0.0f);

    gemm_rowslab_mainloop(A + kbase, M2, Bm + kbase, M2, (M2 / NSPLIT) / 32,
                          smem, smem + 2 * SLAB, acc, tid, wm * 32, wn * 64);

    float* out = d_Spart + ((size_t)((type * B_ + b) * NSPLIT + split)) * (ICH * ICH);
#pragma unroll
    for (int i = 0; i < 2; i++)
#pragma unroll
        for (int j = 0; j < 4; j++)
            wmma::store_matrix_sync(out + (size_t)(wm * 32 + 16 * i) * ICH + wn * 64 + 16 * j,
                                    acc[i][j], ICH, wmma::mem_row_major);
}

// ---------------------------------------------------------------------------
// Deterministic split-K reduce, folds 1/4096. grid (64, 2*B_), block 256
// ---------------------------------------------------------------------------
__global__ __launch_bounds__(256) void s_reduce_kernel()
{
    const int e = blockIdx.x * 256 + threadIdx.x;
    const int mat = blockIdx.y;
    const float* base = d_Spart + (size_t)mat * NSPLIT * (ICH * ICH) + e;
    float s = 0.0f;
#pragma unroll
    for (int sp = 0; sp < NSPLIT; sp++) s += base[(size_t)sp * (ICH * ICH)];
    d_S[(size_t)mat * (ICH * ICH) + e] = s * (1.0f / 4096.0f);
}

// ---------------------------------------------------------------------------
// C[i,p] = sum_k S[k,i] * Tm[k,p]  (S^T @ Tm), tile 128x128 of (128,4096).
// grid (32, 2, B_); K = 128 (4 pipelined 32-slabs), conflict-free K-major smem.
// ---------------------------------------------------------------------------
__global__ __launch_bounds__(256, 2) void out_small_tc()
{
    extern __shared__ float smem[];     // Ss[2][32][132] | Ts[2][32][132]
    float* Ss = smem;
    float* Ts = smem + 2 * SLAB2;
    const int p0 = blockIdx.x * 128, type = blockIdx.y, b = blockIdx.z;
    const float* S  = d_S + (size_t)(type * B_ + b) * (ICH * ICH);
    const float* Tm = (type ? d_phi : d_theta) + (size_t)b * BSTRIDE;
    float* Y = (type ? d_ndT : d_naT) + (size_t)b * BSTRIDE;
    const int tid = threadIdx.x, wid = tid >> 5;
    const int wm = wid & 3, wn = wid >> 2;
    const int iw = wm * 32, pwl = wn * 64;

    FRAG_ACC acc[2][4];
#pragma unroll
    for (int i = 0; i < 2; i++)
#pragma unroll
        for (int j = 0; j < 4; j++) wmma::fill_fragment(acc[i][j], 0.0f);

    load_slab132(Ss, S, ICH, 0, tid);
    load_slab132(Ts, Tm + p0, M2, 0, tid);
    cp_commit();
    const int NT = ICH / 32;            // 4
    for (int kt = 0; kt < NT; kt++) {
        const int cur = kt & 1;
        if (kt + 1 < NT) {
            load_slab132(Ss + ((kt + 1) & 1) * SLAB2, S, ICH, (kt + 1) * 32, tid);
            load_slab132(Ts + ((kt + 1) & 1) * SLAB2, Tm + p0, M2, (kt + 1) * 32, tid);
            cp_commit();
            cp_wait<1>();
        } else {
            cp_wait<0>();
        }
        __syncthreads();
        const float* Sb = Ss + cur * SLAB2;
        const float* Tb = Ts + cur * SLAB2;
#pragma unroll
        for (int ks = 0; ks < 4; ks++) {
            const int kk = ks * 8;
            FRAG_A_C a[2];              // (i,k) at Sb[kk*132 + i]
            FRAG_B_R bf[4];             // (k,p) at Tb[kk*132 + p]
#pragma unroll
            for (int i = 0; i < 2; i++) {
                wmma::load_matrix_sync(a[i], Sb + kk * LDS2 + iw + 16 * i, LDS2);
                cvt_tf32(a[i]);
            }
#pragma unroll
            for (int j = 0; j < 4; j++) {
                wmma::load_matrix_sync(bf[j], Tb + kk * LDS2 + pwl + 16 * j, LDS2);
                cvt_tf32(bf[j]);
            }
#pragma unroll
            for (int i = 0; i < 2; i++)
#pragma unroll
                for (int j = 0; j < 4; j++) wmma::mma_sync(acc[i][j], a[i], bf[j], acc[i][j]);
        }
        __syncthreads();
    }
#pragma unroll
    for (int i = 0; i < 2; i++)
#pragma unroll
        for (int j = 0; j < 4; j++)
            wmma::store_matrix_sync(Y + (size_t)(iw + 16 * i) * M2 + p0 + pwl + 16 * j,
                                    acc[i][j], M2, wmma::mem_row_major);
}

// ---------------------------------------------------------------------------
// Final linears + residual. z=0: Q(ndT)+detect -> out_det ; z=1: W(naT)+aim.
// grid (64, 2, 2)
// ---------------------------------------------------------------------------
__global__ __launch_bounds__(256, 2) void lin2_tc(
    const float* __restrict__ Qw, const float* __restrict__ Qb, const float* __restrict__ det,
    const float* __restrict__ Ww, const float* __restrict__ Wb, const float* __restrict__ aim,
    float* __restrict__ out_det, float* __restrict__ out_aim)
{
    extern __shared__ float smem[];
    __shared__ float patch[8][16][20];
    const int z = blockIdx.z;
    const float* X = z ? d_naT : d_ndT;
    const float* W = z ? Ww : Qw;
    const float* bias = z ? Wb : Qb;
    const float* res  = z ? aim : det;
    float* Y = z ? out_aim : out_det;

    const int tid = threadIdx.x, wid = tid >> 5, lane = tid & 31;
    const int wm = wid & 3, wn = wid >> 2;

    FRAG_ACC acc[2][4];
#pragma unroll
    for (int i = 0; i < 2; i++)
#pragma unroll
        for (int j = 0; j < 4; j++) wmma::fill_fragment(acc[i][j], 0.0f);

    const float* Xt = X + (size_t)(blockIdx.x * 128) * CD;
    const float* Wt = W + (size_t)(blockIdx.y * 128) * CD;
    gemm_rowslab_mainloop(Xt, CD, Wt, CD, CD / 32, smem, smem + 2 * SLAB,
                          acc, tid, wm * 32, wn * 64);

    const int m0 = blockIdx.x * 128 + wm * 32;
    const int n0 = blockIdx.y * 128 + wn * 64;
    const int pr = lane & 15, pc = (lane >> 4) * 8;
#pragma unroll
    for (int i = 0; i < 2; i++)
#pragma unroll
        for (int j = 0; j < 4; j++) {
            wmma::store_matrix_sync(&patch[wid][0][0], acc[i][j], 20, wmma::mem_row_major);
            __syncwarp();
            const int m = m0 + 16 * i + pr;
            const int nb = n0 + 16 * j + pc;
            const float* rrow = &res[(size_t)m * CD + nb];
            float r[8];
#pragma unroll
            for (int t = 0; t < 8; t++)
                r[t] = patch[wid][pr][pc + t] + bias[nb + t] + rrow[t];
            float* row = &Y[(size_t)m * CD + nb];
            *(float4*)(row)     = make_float4(r[0], r[1], r[2], r[3]);
            *(float4*)(row + 4) = make_float4(r[4], r[5], r[6], r[7]);
            __syncwarp();
        }
}

// ---------------------------------------------------------------------------
extern "C" void kernel_launch(void* const* d_in, const int* in_sizes, int n_in,
                              void* d_out, int out_size)
{
    const float* detect = (const float*)d_in[0];
    const float* aim    = (const float*)d_in[1];
    const float* g_w  = (const float*)d_in[2];  const float* g_b  = (const float*)d_in[3];
    const float* g2_w = (const float*)d_in[4];  const float* g2_b = (const float*)d_in[5];
    const float* th_w = (const float*)d_in[6];  const float* th_b = (const float*)d_in[7];
    const float* ph_w = (const float*)d_in[8];  const float* ph_b = (const float*)d_in[9];
    const float* W_w  = (const float*)d_in[10]; const float* W_b  = (const float*)d_in[11];
    const float* Q_w  = (const float*)d_in[12]; const float* Q_b  = (const float*)d_in[13];

    float* out_det = (float*)d_out;
    float* out_aim = out_det + (size_t)B_ * NSEQ * CD;

    const int smemLin = 4 * SLAB * (int)sizeof(float);     // 73728
    const int smemOut = 4 * SLAB2 * (int)sizeof(float);    // 67584
    cudaFuncSetAttribute(lin4_tc,      cudaFuncAttributeMaxDynamicSharedMemorySize, smemLin);
    cudaFuncSetAttribute(s_partial_tc, cudaFuncAttributeMaxDynamicSharedMemorySize, smemLin);
    cudaFuncSetAttribute(out_small_tc, cudaFuncAttributeMaxDynamicSharedMemorySize, smemOut);
    cudaFuncSetAttribute(lin2_tc,      cudaFuncAttributeMaxDynamicSharedMemorySize, smemLin);

    lin4_tc<<<dim3(64, 2, 4), 256, smemLin>>>(
        detect, g_w,  g_b,
        aim,    g2_w, g2_b,
        aim,    th_w, th_b,
        detect, ph_w, ph_b);

    s_partial_tc<<<dim3(NSPLIT, 2, B_), 256, smemLin>>>();
    s_reduce_kernel<<<dim3(64, 2 * B_), 256>>>();

    out_small_tc<<<dim3(M2 / 128, 2, B_), 256, smemOut>>>();

    lin2_tc<<<dim3(64, 2, 2), 256, smemLin>>>(
        Q_w, Q_b, detect, W_w, W_b, aim, out_det, out_aim);
}

// round 6
// speedup vs baseline: 24.1910x; 2.3297x over previous
#include <cuda_runtime.h>
#include <cuda_bf16.h>
#include <mma.h>
#include <cstddef>
#include <cstdint>

using namespace nvcuda;
typedef __nv_bfloat16 bf16;

#define B_    4
#define NSEQ  2048
#define CD    256
#define ICH   128
#define M2    4096                    // 2*NSEQ
#define LIN_ELEMS (B_*NSEQ*CD)        // 2,097,152
#define BSTRIDE   (NSEQ*CD)           // 524,288 per batch
#define NSPLIT    16

// bf16 copies of inputs/weights
__device__ bf16 h_det[LIN_ELEMS];
__device__ bf16 h_aim[LIN_ELEMS];
__device__ bf16 h_wg [CD*CD];
__device__ bf16 h_wg2[CD*CD];
__device__ bf16 h_wth[CD*CD];
__device__ bf16 h_wph[CD*CD];
__device__ bf16 h_wW [CD*CD];
__device__ bf16 h_wQ [CD*CD];
// intermediates (bf16)
__device__ bf16 h_g    [LIN_ELEMS];
__device__ bf16 h_g2   [LIN_ELEMS];
__device__ bf16 h_theta[LIN_ELEMS];
__device__ bf16 h_phi  [LIN_ELEMS];
__device__ bf16 h_S    [2*B_*ICH*ICH];            // scaled by 1/4096
__device__ bf16 h_naT  [LIN_ELEMS];
__device__ bf16 h_ndT  [LIN_ELEMS];
// fp32 split-K partials (precision)
__device__ float d_Spart[2*B_*NSPLIT*ICH*ICH];

typedef wmma::fragment<wmma::matrix_a, 16, 16, 16, bf16, wmma::row_major> FA_R;
typedef wmma::fragment<wmma::matrix_a, 16, 16, 16, bf16, wmma::col_major> FA_C;
typedef wmma::fragment<wmma::matrix_b, 16, 16, 16, bf16, wmma::row_major> FB_R;
typedef wmma::fragment<wmma::matrix_b, 16, 16, 16, bf16, wmma::col_major> FB_C;
typedef wmma::fragment<wmma::accumulator, 16, 16, 16, float>              FACC;

// ---- cp.async helpers -----------------------------------------------------
__device__ __forceinline__ void cp16(void* s, const void* g) {
    uint32_t sa = (uint32_t)__cvta_generic_to_shared(s);
    asm volatile("cp.async.cg.shared.global [%0], [%1], 16;\n" :: "r"(sa), "l"(g));
}
__device__ __forceinline__ void cp_commit() { asm volatile("cp.async.commit_group;\n"); }
template <int N>
__device__ __forceinline__ void cp_wait() { asm volatile("cp.async.wait_group %0;\n" :: "n"(N)); }

// Row-slab: [128 rows][40 (=32 K + 8 pad)] bf16 -> 80B rows, ldmatrix conflict-free
#define PAD_H  40
#define SLAB_H (128*PAD_H)
// K-slab (out_small): [32 K][136 (=128 + 8 pad)] bf16
#define PAD2_H  136
#define SLAB2_H (32*PAD2_H)

// 256 threads copy 128x32 bf16 tile, rows from gmem with leading dim ldg
__device__ __forceinline__ void load_slab_h(bf16* dst, const bf16* src, size_t ldg,
                                            int k0, int t)
{
    const int row = t >> 1, c0 = (t & 1) * 16;
    const bf16* g = src + (size_t)row * ldg + k0 + c0;
    bf16* s = dst + row * PAD_H + c0;
    cp16(s, g); cp16(s + 8, g + 8);
}

// 256 threads copy 32x128 bf16 tile (K-major rows), leading dim ldg
__device__ __forceinline__ void load_slab2_h(bf16* dst, const bf16* src, size_t ldg,
                                             int k0, int t)
{
    const int kk = t >> 3, c0 = (t & 7) * 16;
    const bf16* g = src + (size_t)(k0 + kk) * ldg + c0;
    bf16* s = dst + kk * PAD2_H + c0;
    cp16(s, g); cp16(s + 8, g + 8);
}

// Mainloop: C[128x128] += A(rowslab) x B(rowslab)^T, K = NT*32, bf16 MMA.
__device__ __forceinline__ void mainloop_h(
    const bf16* Xt, size_t ldx, const bf16* Wt, size_t ldw, int NT,
    bf16* As, bf16* Bs, FACC (&acc)[2][4], int tid, int mwl, int nwl)
{
    load_slab_h(As, Xt, ldx, 0, tid);
    load_slab_h(Bs, Wt, ldw, 0, tid);
    cp_commit();
    for (int kt = 0; kt < NT; kt++) {
        const int cur = kt & 1;
        if (kt + 1 < NT) {
            load_slab_h(As + ((kt + 1) & 1) * SLAB_H, Xt, ldx, (kt + 1) * 32, tid);
            load_slab_h(Bs + ((kt + 1) & 1) * SLAB_H, Wt, ldw, (kt + 1) * 32, tid);
            cp_commit();
            cp_wait<1>();
        } else {
            cp_wait<0>();
        }
        __syncthreads();
        const bf16* Ab = As + cur * SLAB_H;
        const bf16* Bb = Bs + cur * SLAB_H;
#pragma unroll
        for (int ks = 0; ks < 2; ks++) {
            const int kk = ks * 16;
            FA_R a[2];
            FB_C b[4];
#pragma unroll
            for (int i = 0; i < 2; i++)
                wmma::load_matrix_sync(a[i], Ab + (mwl + 16 * i) * PAD_H + kk, PAD_H);
#pragma unroll
            for (int j = 0; j < 4; j++)
                wmma::load_matrix_sync(b[j], Bb + (nwl + 16 * j) * PAD_H + kk, PAD_H);
#pragma unroll
            for (int i = 0; i < 2; i++)
#pragma unroll
                for (int j = 0; j < 4; j++) wmma::mma_sync(acc[i][j], a[i], b[j], acc[i][j]);
        }
        __syncthreads();
    }
}

// ---------------------------------------------------------------------------
// fp32 -> bf16 conversion of inputs + weights. grid (1024, 8), block 256.
// z: 0=detect,1=aim,2..7 = weights g,g2,theta,phi,W,Q
// ---------------------------------------------------------------------------
__global__ __launch_bounds__(256) void cvt_kernel(
    const float* __restrict__ det, const float* __restrict__ aim,
    const float* __restrict__ w0, const float* __restrict__ w1,
    const float* __restrict__ w2, const float* __restrict__ w3,
    const float* __restrict__ w4, const float* __restrict__ w5)
{
    const int z = blockIdx.y;
    const float* src; bf16* dst; int n;
    if      (z == 0) { src = det; dst = h_det; n = LIN_ELEMS; }
    else if (z == 1) { src = aim; dst = h_aim; n = LIN_ELEMS; }
    else if (z == 2) { src = w0; dst = h_wg;  n = CD*CD; }
    else if (z == 3) { src = w1; dst = h_wg2; n = CD*CD; }
    else if (z == 4) { src = w2; dst = h_wth; n = CD*CD; }
    else if (z == 5) { src = w3; dst = h_wph; n = CD*CD; }
    else if (z == 6) { src = w4; dst = h_wW;  n = CD*CD; }
    else             { src = w5; dst = h_wQ;  n = CD*CD; }
    const int idx = (blockIdx.x * 256 + threadIdx.x) * 8;
    if (idx >= n) return;
    float4 v0 = *(const float4*)&src[idx];
    float4 v1 = *(const float4*)&src[idx + 4];
    uint4 o;
    __nv_bfloat162* op = (__nv_bfloat162*)&o;
    op[0] = __floats2bfloat162_rn(v0.x, v0.y);
    op[1] = __floats2bfloat162_rn(v0.z, v0.w);
    op[2] = __floats2bfloat162_rn(v1.x, v1.y);
    op[3] = __floats2bfloat162_rn(v1.z, v1.w);
    *(uint4*)&dst[idx] = o;
}

// ---------------------------------------------------------------------------
// Front linears (bf16): Y = X[8192,256] @ W^T + bias, bf16 out. grid (64,2,4)
// ---------------------------------------------------------------------------
__global__ __launch_bounds__(256, 2) void lin4_tc(
    const float* __restrict__ b0, const float* __restrict__ b1,
    const float* __restrict__ b2, const float* __restrict__ b3)
{
    extern __shared__ bf16 smem[];
    __shared__ float patch[8][16][20];
    const int z = blockIdx.z;
    const bf16* X; const bf16* W; const float* bias; bf16* Y;
    if      (z == 0) { X = h_det; W = h_wg;  bias = b0; Y = h_g;     }
    else if (z == 1) { X = h_aim; W = h_wg2; bias = b1; Y = h_g2;    }
    else if (z == 2) { X = h_aim; W = h_wth; bias = b2; Y = h_theta; }
    else             { X = h_det; W = h_wph; bias = b3; Y = h_phi;   }

    const int tid = threadIdx.x, wid = tid >> 5, lane = tid & 31;
    const int wm = wid & 3, wn = wid >> 2;

    FACC acc[2][4];
#pragma unroll
    for (int i = 0; i < 2; i++)
#pragma unroll
        for (int j = 0; j < 4; j++) wmma::fill_fragment(acc[i][j], 0.0f);

    mainloop_h(X + (size_t)(blockIdx.x * 128) * CD, CD,
               W + (size_t)(blockIdx.y * 128) * CD, CD, CD / 32,
               smem, smem + 2 * SLAB_H, acc, tid, wm * 32, wn * 64);

    const int m0 = blockIdx.x * 128 + wm * 32;
    const int n0 = blockIdx.y * 128 + wn * 64;
    const int pr = lane & 15, pc = (lane >> 4) * 8;
#pragma unroll
    for (int i = 0; i < 2; i++)
#pragma unroll
        for (int j = 0; j < 4; j++) {
            wmma::store_matrix_sync(&patch[wid][0][0], acc[i][j], 20, wmma::mem_row_major);
            __syncwarp();
            const int m = m0 + 16 * i + pr;
            const int nb = n0 + 16 * j + pc;
            uint4 o;
            __nv_bfloat162* op = (__nv_bfloat162*)&o;
#pragma unroll
            for (int t = 0; t < 4; t++)
                op[t] = __floats2bfloat162_rn(patch[wid][pr][pc + 2*t]     + bias[nb + 2*t],
                                              patch[wid][pr][pc + 2*t + 1] + bias[nb + 2*t + 1]);
            *(uint4*)&Y[(size_t)m * CD + nb] = o;
            __syncwarp();
        }
}

// ---------------------------------------------------------------------------
// Split-K partials (fp32 out): type 0: S1 = Ph @ Gr^T ; 1: S2 = Th @ A2^T
// grid (NSPLIT, 2, B_)
// ---------------------------------------------------------------------------
__global__ __launch_bounds__(256, 2) void s_partial_tc()
{
    extern __shared__ bf16 smem[];
    const int split = blockIdx.x, type = blockIdx.y, b = blockIdx.z;
    const bf16* A  = (type ? h_theta : h_phi) + (size_t)b * BSTRIDE;
    const bf16* Bm = (type ? h_g2   : h_g  ) + (size_t)b * BSTRIDE;
    const int kbase = split * (M2 / NSPLIT);
    const int tid = threadIdx.x, wid = tid >> 5;
    const int wm = wid & 3, wn = wid >> 2;

    FACC acc[2][4];
#pragma unroll
    for (int i = 0; i < 2; i++)
#pragma unroll
        for (int j = 0; j < 4; j++) wmma::fill_fragment(acc[i][j], 0.0f);

    mainloop_h(A + kbase, M2, Bm + kbase, M2, (M2 / NSPLIT) / 32,
               smem, smem + 2 * SLAB_H, acc, tid, wm * 32, wn * 64);

    float* out = d_Spart + ((size_t)((type * B_ + b) * NSPLIT + split)) * (ICH * ICH);
#pragma unroll
    for (int i = 0; i < 2; i++)
#pragma unroll
        for (int j = 0; j < 4; j++)
            wmma::store_matrix_sync(out + (size_t)(wm * 32 + 16 * i) * ICH + wn * 64 + 16 * j,
                                    acc[i][j], ICH, wmma::mem_row_major);
}

// ---------------------------------------------------------------------------
// Deterministic reduce (fp32 sum), scale by 1/4096, write bf16.
// grid (64, 2*B_), block 256
// ---------------------------------------------------------------------------
__global__ __launch_bounds__(256) void s_reduce_kernel()
{
    const int e = blockIdx.x * 256 + threadIdx.x;
    const int mat = blockIdx.y;
    const float* base = d_Spart + (size_t)mat * NSPLIT * (ICH * ICH) + e;
    float s = 0.0f;
#pragma unroll
    for (int sp = 0; sp < NSPLIT; sp++) s += base[(size_t)sp * (ICH * ICH)];
    h_S[(size_t)mat * (ICH * ICH) + e] = __float2bfloat16(s * (1.0f / 4096.0f));
}

// ---------------------------------------------------------------------------
// C[i,p] = sum_k S[k,i] * Tm[k,p]  (S^T @ Tm), bf16 in/out.
// grid (32, 2, B_); K = 128 in 4 pipelined 32-K slabs (K-major smem).
// ---------------------------------------------------------------------------
__global__ __launch_bounds__(256, 2) void out_small_tc()
{
    extern __shared__ bf16 smem[];      // Ss[2][32][136] | Ts[2][32][136]
    bf16* Ss = smem;
    bf16* Ts = smem + 2 * SLAB2_H;
    __shared__ float patch[8][16][20];
    const int p0 = blockIdx.x * 128, type = blockIdx.y, b = blockIdx.z;
    const bf16* S  = h_S + (size_t)(type * B_ + b) * (ICH * ICH);
    const bf16* Tm = (type ? h_phi : h_theta) + (size_t)b * BSTRIDE;
    bf16* Y = (type ? h_ndT : h_naT) + (size_t)b * BSTRIDE;
    const int tid = threadIdx.x, wid = tid >> 5, lane = tid & 31;
    const int wm = wid & 3, wn = wid >> 2;
    const int iw = wm * 32, pwl = wn * 64;

    FACC acc[2][4];
#pragma unroll
    for (int i = 0; i < 2; i++)
#pragma unroll
        for (int j = 0; j < 4; j++) wmma::fill_fragment(acc[i][j], 0.0f);

    load_slab2_h(Ss, S, ICH, 0, tid);
    load_slab2_h(Ts, Tm + p0, M2, 0, tid);
    cp_commit();
    const int NT = ICH / 32;            // 4
    for (int kt = 0; kt < NT; kt++) {
        const int cur = kt & 1;
        if (kt + 1 < NT) {
            load_slab2_h(Ss + ((kt + 1) & 1) * SLAB2_H, S, ICH, (kt + 1) * 32, tid);
            load_slab2_h(Ts + ((kt + 1) & 1) * SLAB2_H, Tm + p0, M2, (kt + 1) * 32, tid);
            cp_commit();
            cp_wait<1>();
        } else {
            cp_wait<0>();
        }
        __syncthreads();
        const bf16* Sb = Ss + cur * SLAB2_H;
        const bf16* Tb = Ts + cur * SLAB2_H;
#pragma unroll
        for (int ks = 0; ks < 2; ks++) {
            const int kk = ks * 16;
            FA_C a[2];                  // (i,k) at Sb[kk*136 + i]
            FB_R bf[4];                 // (k,p) at Tb[kk*136 + p]
#pragma unroll
            for (int i = 0; i < 2; i++)
                wmma::load_matrix_sync(a[i], Sb + kk * PAD2_H + iw + 16 * i, PAD2_H);
#pragma unroll
            for (int j = 0; j < 4; j++)
                wmma::load_matrix_sync(bf[j], Tb + kk * PAD2_H + pwl + 16 * j, PAD2_H);
#pragma unroll
            for (int i = 0; i < 2; i++)
#pragma unroll
                for (int j = 0; j < 4; j++) wmma::mma_sync(acc[i][j], a[i], bf[j], acc[i][j]);
        }
        __syncthreads();
    }
    const int pr = lane & 15, pc = (lane >> 4) * 8;
#pragma unroll
    for (int i = 0; i < 2; i++)
#pragma unroll
        for (int j = 0; j < 4; j++) {
            wmma::store_matrix_sync(&patch[wid][0][0], acc[i][j], 20, wmma::mem_row_major);
            __syncwarp();
            const int r = iw + 16 * i + pr;
            const int c = p0 + pwl + 16 * j + pc;
            uint4 o;
            __nv_bfloat162* op = (__nv_bfloat162*)&o;
#pragma unroll
            for (int t = 0; t < 4; t++)
                op[t] = __floats2bfloat162_rn(patch[wid][pr][pc + 2*t], patch[wid][pr][pc + 2*t + 1]);
            *(uint4*)&Y[(size_t)r * M2 + c] = o;
            __syncwarp();
        }
}

// ---------------------------------------------------------------------------
// Final linears + residual (fp32 out). z=0: Q(ndT)+detect ; z=1: W(naT)+aim.
// grid (64, 2, 2)
// ---------------------------------------------------------------------------
__global__ __launch_bounds__(256, 2) void lin2_tc(
    const float* __restrict__ Qb, const float* __restrict__ det,
    const float* __restrict__ Wb, const float* __restrict__ aim,
    float* __restrict__ out_det, float* __restrict__ out_aim)
{
    extern __shared__ bf16 smem[];
    __shared__ float patch[8][16][20];
    const int z = blockIdx.z;
    const bf16* X = z ? h_naT : h_ndT;
    const bf16* W = z ? h_wW : h_wQ;
    const float* bias = z ? Wb : Qb;
    const float* res  = z ? aim : det;
    float* Y = z ? out_aim : out_det;

    const int tid = threadIdx.x, wid = tid >> 5, lane = tid & 31;
    const int wm = wid & 3, wn = wid >> 2;

    FACC acc[2][4];
#pragma unroll
    for (int i = 0; i < 2; i++)
#pragma unroll
        for (int j = 0; j < 4; j++) wmma::fill_fragment(acc[i][j], 0.0f);

    mainloop_h(X + (size_t)(blockIdx.x * 128) * CD, CD,
               W + (size_t)(blockIdx.y * 128) * CD, CD, CD / 32,
               smem, smem + 2 * SLAB_H, acc, tid, wm * 32, wn * 64);

    const int m0 = blockIdx.x * 128 + wm * 32;
    const int n0 = blockIdx.y * 128 + wn * 64;
    const int pr = lane & 15, pc = (lane >> 4) * 8;
#pragma unroll
    for (int i = 0; i < 2; i++)
#pragma unroll
        for (int j = 0; j < 4; j++) {
            wmma::store_matrix_sync(&patch[wid][0][0], acc[i][j], 20, wmma::mem_row_major);
            __syncwarp();
            const int m = m0 + 16 * i + pr;
            const int nb = n0 + 16 * j + pc;
            const float* rrow = &res[(size_t)m * CD + nb];
            float r[8];
#pragma unroll
            for (int t = 0; t < 8; t++)
                r[t] = patch[wid][pr][pc + t] + bias[nb + t] + rrow[t];
            float* row = &Y[(size_t)m * CD + nb];
            *(float4*)(row)     = make_float4(r[0], r[1], r[2], r[3]);
            *(float4*)(row + 4) = make_float4(r[4], r[5], r[6], r[7]);
            __syncwarp();
        }
}

// ---------------------------------------------------------------------------
extern "C" void kernel_launch(void* const* d_in, const int* in_sizes, int n_in,
                              void* d_out, int out_size)
{
    const float* detect = (const float*)d_in[0];
    const float* aim    = (const float*)d_in[1];
    const float* g_w  = (const float*)d_in[2];  const float* g_b  = (const float*)d_in[3];
    const float* g2_w = (const float*)d_in[4];  const float* g2_b = (const float*)d_in[5];
    const float* th_w = (const float*)d_in[6];  const float* th_b = (const float*)d_in[7];
    const float* ph_w = (const float*)d_in[8];  const float* ph_b = (const float*)d_in[9];
    const float* W_w  = (const float*)d_in[10]; const float* W_b  = (const float*)d_in[11];
    const float* Q_w  = (const float*)d_in[12]; const float* Q_b  = (const float*)d_in[13];

    float* out_det = (float*)d_out;
    float* out_aim = out_det + (size_t)B_ * NSEQ * CD;

    const int smemLin = 4 * SLAB_H * (int)sizeof(bf16);    // 40960
    const int smemOut = 4 * SLAB2_H * (int)sizeof(bf16);   // 34816
    cudaFuncSetAttribute(lin4_tc,      cudaFuncAttributeMaxDynamicSharedMemorySize, smemLin);
    cudaFuncSetAttribute(s_partial_tc, cudaFuncAttributeMaxDynamicSharedMemorySize, smemLin);
    cudaFuncSetAttribute(out_small_tc, cudaFuncAttributeMaxDynamicSharedMemorySize, smemOut);
    cudaFuncSetAttribute(lin2_tc,      cudaFuncAttributeMaxDynamicSharedMemorySize, smemLin);

    // Stage 0: fp32 -> bf16 for inputs + weights
    cvt_kernel<<<dim3(LIN_ELEMS / (256 * 8), 8), 256>>>(
        detect, aim, g_w, g2_w, th_w, ph_w, W_w, Q_w);

    // Stage 1: four front linears (bf16 in/out)
    lin4_tc<<<dim3(64, 2, 4), 256, smemLin>>>(g_b, g2_b, th_b, ph_b);

    // Stage 2: S1/S2 split-K + reduce (+1/4096, bf16 out)
    s_partial_tc<<<dim3(NSPLIT, 2, B_), 256, smemLin>>>();
    s_reduce_kernel<<<dim3(64, 2 * B_), 256>>>();

    // Stage 3: naT/ndT (bf16)
    out_small_tc<<<dim3(M2 / 128, 2, B_), 256, smemOut>>>();

    // Stage 4: final linears + residuals (fp32 out)
    lin2_tc<<<dim3(64, 2, 2), 256, smemLin>>>(
        Q_b, detect, W_b, aim, out_det, out_aim);
}